// round 1
// baseline (speedup 1.0000x reference)
#include <cuda_runtime.h>
#include <cuda_bf16.h>
#include <math.h>

// Problem constants
#define Bb 128
#define Tt 32
#define Ee 512
#define Hh 512
#define Ll 256
#define Vv 16000

// Output layout (pytree leaf order): p_mus, p_sigmas, q_mus, q_sigmas, q_xs
#define OFF_PMU  ((size_t)0)
#define OFF_PSIG ((size_t)Tt * Bb * Ll)
#define OFF_QMU  ((size_t)2 * Tt * Bb * Ll)
#define OFF_QSIG ((size_t)3 * Tt * Bb * Ll)
#define OFF_QX   ((size_t)4 * Tt * Bb * Ll)

// ---------------- device scratch (static, allocation-free) ----------------
__device__ float g_emb[Tt * Bb * Ee];            // [T,B,E] gathered embeddings
__device__ float g_Wcat[4 * Hh * (Ee + Ll + Hh)]; // [2048, 1280] = [W_ih | W_hh]
__device__ float g_bsum[4 * Hh];                 // b_ih + b_hh
__device__ float g_h[Bb * Hh];
__device__ float g_c[Bb * Hh];
__device__ float g_xq[Bb * (Ee + Hh)];           // [e_t, h]   (K=1024)
__device__ float g_xx[Bb * (Ll + Hh)];           // [z, h]     (K=768)
__device__ float g_xcat[Bb * (Ee + Ll + Hh)];    // [e_t, z, h](K=1280)
__device__ float g_gates[Bb * 4 * Hh];           // [128, 2048]

__device__ __forceinline__ float sigf(float x) { return 1.0f / (1.0f + expf(-x)); }

// ---------------- prep: Wcat, bsum, embedding gather ----------------
__global__ void prep_kernel(const float* __restrict__ W_ih, const float* __restrict__ W_hh,
                            const float* __restrict__ b_ih, const float* __restrict__ b_hh,
                            const float* __restrict__ embed_W, const int* __restrict__ captions) {
    const int N_WCAT = 4 * Hh * (Ee + Ll + Hh);   // 2048*1280
    const int N_BS = 4 * Hh;
    const int N_EMB = Tt * Bb * Ee;
    int idx = blockIdx.x * blockDim.x + threadIdx.x;
    if (idx < N_WCAT) {
        int n = idx / (Ee + Ll + Hh);
        int k = idx % (Ee + Ll + Hh);
        float v = (k < Ee + Ll) ? W_ih[n * (Ee + Ll) + k] : W_hh[n * Hh + (k - (Ee + Ll))];
        g_Wcat[idx] = v;
    } else if (idx < N_WCAT + N_BS) {
        int n = idx - N_WCAT;
        g_bsum[n] = b_ih[n] + b_hh[n];
    } else if (idx < N_WCAT + N_BS + N_EMB) {
        int j = idx - N_WCAT - N_BS;
        int tb = j / Ee;                  // t*B + b
        int e = j % Ee;
        int t = tb / Bb, b = tb % Bb;
        int cap = captions[b * Tt + t];
        g_emb[j] = embed_W[(size_t)cap * Ee + e];
    }
}

__global__ void zero_c_kernel() {
    int idx = blockIdx.x * blockDim.x + threadIdx.x;
    if (idx < Bb * Hh) g_c[idx] = 0.0f;
}

// ---------------- SGEMM: C = A[M,K] * B[N,K]^T + bias, with column-split output ----------------
template <int BM, int BN, int BK, int TM, int TN>
__global__ void sgemm_bt(const float* __restrict__ A, int lda,
                         const float* __restrict__ Bw, int ldb,
                         const float* __restrict__ bias,
                         float* __restrict__ C0, int ldc0,
                         float* __restrict__ C1, int ldc1, int splitN,
                         int M, int N, int K) {
    constexpr int THREADS = (BM / TM) * (BN / TN);
    __shared__ float As[BK][BM];
    __shared__ float Bs[BK][BN];
    const int tid = threadIdx.x;
    const int block_m = blockIdx.x * BM;
    const int block_n = blockIdx.y * BN;
    const int tn_ = tid % (BN / TN);
    const int tm_ = tid / (BN / TN);

    float acc[TM][TN];
#pragma unroll
    for (int i = 0; i < TM; i++)
#pragma unroll
        for (int j = 0; j < TN; j++) acc[i][j] = 0.0f;

    constexpr int A_F4 = BM * BK / 4;
    constexpr int B_F4 = BN * BK / 4;

    for (int k0 = 0; k0 < K; k0 += BK) {
#pragma unroll
        for (int i = tid; i < A_F4; i += THREADS) {
            int row = i / (BK / 4);
            int kq = i % (BK / 4);
            float4 v = *(const float4*)(A + (size_t)(block_m + row) * lda + k0 + kq * 4);
            As[kq * 4 + 0][row] = v.x;
            As[kq * 4 + 1][row] = v.y;
            As[kq * 4 + 2][row] = v.z;
            As[kq * 4 + 3][row] = v.w;
        }
#pragma unroll
        for (int i = tid; i < B_F4; i += THREADS) {
            int row = i / (BK / 4);
            int kq = i % (BK / 4);
            float4 v = *(const float4*)(Bw + (size_t)(block_n + row) * ldb + k0 + kq * 4);
            Bs[kq * 4 + 0][row] = v.x;
            Bs[kq * 4 + 1][row] = v.y;
            Bs[kq * 4 + 2][row] = v.z;
            Bs[kq * 4 + 3][row] = v.w;
        }
        __syncthreads();
#pragma unroll
        for (int kk = 0; kk < BK; kk++) {
            float ra[TM], rb[TN];
#pragma unroll
            for (int i = 0; i < TM; i++) ra[i] = As[kk][tm_ * TM + i];
#pragma unroll
            for (int j = 0; j < TN; j++) rb[j] = Bs[kk][tn_ * TN + j];
#pragma unroll
            for (int i = 0; i < TM; i++)
#pragma unroll
                for (int j = 0; j < TN; j++) acc[i][j] = fmaf(ra[i], rb[j], acc[i][j]);
        }
        __syncthreads();
    }

#pragma unroll
    for (int i = 0; i < TM; i++) {
        int m = block_m + tm_ * TM + i;
#pragma unroll
        for (int j = 0; j < TN; j++) {
            int n = block_n + tn_ * TN + j;
            float v = acc[i][j] + bias[n];
            if (n < splitN)
                C0[(size_t)m * ldc0 + n] = v;
            else
                C1[(size_t)m * ldc1 + (n - splitN)] = v;
        }
    }
}

// ---------------- per-step elementwise kernels ----------------
// Fill xq = [e_t, h]; also e into xcat[:, :512], h into xcat[:, 768:1280] and xx[:, 256:768]
__global__ void assembleA_kernel(int t) {
    int idx = blockIdx.x * blockDim.x + threadIdx.x;
    if (idx >= Bb * (Ee + Hh)) return;
    int b = idx / (Ee + Hh);
    int k = idx % (Ee + Hh);
    float v;
    if (k < Ee) {
        v = g_emb[((size_t)t * Bb + b) * Ee + k];
        g_xcat[b * (Ee + Ll + Hh) + k] = v;
    } else {
        int kh = k - Ee;
        v = g_h[b * Hh + kh];
        g_xcat[b * (Ee + Ll + Hh) + Ee + Ll + kh] = v;
        g_xx[b * (Ll + Hh) + Ll + kh] = v;
    }
    g_xq[idx] = v;
}

// z = noise * q_sigma + q_mu; write into xx[:, :256] and xcat[:, 512:768]
__global__ void z_kernel(const float* __restrict__ noise, const float* __restrict__ out, int t) {
    int idx = blockIdx.x * blockDim.x + threadIdx.x;
    if (idx >= Bb * Ll) return;
    int b = idx / Ll, l = idx % Ll;
    size_t o = ((size_t)t * Bb + b) * Ll + l;
    float qm = out[OFF_QMU + o];
    float qs = out[OFF_QSIG + o];
    float z = noise[((size_t)b * Tt + t) * Ll + l] * qs + qm;
    g_xx[b * (Ll + Hh) + l] = z;
    g_xcat[b * (Ee + Ll + Hh) + Ee + l] = z;
}

// LSTM elementwise update from g_gates (PyTorch gate order i,f,g,o)
__global__ void lstm_kernel() {
    int idx = blockIdx.x * blockDim.x + threadIdx.x;
    if (idx >= Bb * Hh) return;
    int b = idx / Hh, n = idx % Hh;
    const float* gr = g_gates + (size_t)b * 4 * Hh;
    float gi = gr[n];
    float gf = gr[Hh + n];
    float gg = gr[2 * Hh + n];
    float go = gr[3 * Hh + n];
    float c = sigf(gf) * g_c[idx] + sigf(gi) * tanhf(gg);
    g_c[idx] = c;
    g_h[idx] = sigf(go) * tanhf(c);
}

// In-place log_softmax over rows of length V (one block per row)
__global__ void logsoftmax_kernel(float* __restrict__ base) {
    float* x = base + (size_t)blockIdx.x * Vv;
    __shared__ float sred[32];
    __shared__ float sval;
    const int tid = threadIdx.x;

    float m = -3.4e38f;
    for (int i = tid; i < Vv; i += 256) m = fmaxf(m, x[i]);
#pragma unroll
    for (int o = 16; o; o >>= 1) m = fmaxf(m, __shfl_xor_sync(0xffffffffu, m, o));
    if ((tid & 31) == 0) sred[tid >> 5] = m;
    __syncthreads();
    if (tid < 32) {
        float v = (tid < 8) ? sred[tid] : -3.4e38f;
#pragma unroll
        for (int o = 4; o; o >>= 1) v = fmaxf(v, __shfl_xor_sync(0xffffffffu, v, o));
        if (tid == 0) sval = v;
    }
    __syncthreads();
    m = sval;

    float s = 0.0f;
    for (int i = tid; i < Vv; i += 256) s += expf(x[i] - m);
#pragma unroll
    for (int o = 16; o; o >>= 1) s += __shfl_xor_sync(0xffffffffu, s, o);
    __syncthreads();
    if ((tid & 31) == 0) sred[tid >> 5] = s;
    __syncthreads();
    if (tid < 32) {
        float v = (tid < 8) ? sred[tid] : 0.0f;
#pragma unroll
        for (int o = 4; o; o >>= 1) v += __shfl_xor_sync(0xffffffffu, v, o);
        if (tid == 0) sval = m + logf(v);
    }
    __syncthreads();
    float lz = sval;
    for (int i = tid; i < Vv; i += 256) x[i] -= lz;
}

// ---------------- host-side launch helpers ----------------
static inline void gemm_small(const float* A, int lda, const float* Bw, int ldb, const float* bias,
                              float* C0, int ldc0, float* C1, int ldc1, int splitN,
                              int M, int N, int K) {
    dim3 grid(M / 32, N / 64);
    sgemm_bt<32, 64, 8, 4, 4><<<grid, 128>>>(A, lda, Bw, ldb, bias, C0, ldc0, C1, ldc1, splitN, M, N, K);
}
static inline void gemm_big(const float* A, int lda, const float* Bw, int ldb, const float* bias,
                            float* C0, int ldc0, float* C1, int ldc1, int splitN,
                            int M, int N, int K) {
    dim3 grid(M / 64, N / 128);
    sgemm_bt<64, 128, 8, 8, 8><<<grid, 128>>>(A, lda, Bw, ldb, bias, C0, ldc0, C1, ldc1, splitN, M, N, K);
}

extern "C" void kernel_launch(void* const* d_in, const int* in_sizes, int n_in,
                              void* d_out, int out_size) {
    const float* features = (const float*)d_in[0];
    const int* captions = (const int*)d_in[1];
    // d_in[2] lengths: unused (all == T)
    const float* noise   = (const float*)d_in[3];
    const float* embed_W = (const float*)d_in[4];
    const float* W_ih    = (const float*)d_in[5];
    const float* W_hh    = (const float*)d_in[6];
    const float* b_ih    = (const float*)d_in[7];
    const float* b_hh    = (const float*)d_in[8];
    const float* qz_W    = (const float*)d_in[9];
    const float* qz_b    = (const float*)d_in[10];
    const float* prior_W = (const float*)d_in[11];
    const float* prior_b = (const float*)d_in[12];
    const float* qx_W    = (const float*)d_in[13];
    const float* qx_b    = (const float*)d_in[14];
    float* out = (float*)d_out;

    float *pemb, *pWcat, *pbsum, *ph, *pc, *pxq, *pxx, *pxcat, *pgates;
    cudaGetSymbolAddress((void**)&pemb, g_emb);
    cudaGetSymbolAddress((void**)&pWcat, g_Wcat);
    cudaGetSymbolAddress((void**)&pbsum, g_bsum);
    cudaGetSymbolAddress((void**)&ph, g_h);
    cudaGetSymbolAddress((void**)&pc, g_c);
    cudaGetSymbolAddress((void**)&pxq, g_xq);
    cudaGetSymbolAddress((void**)&pxx, g_xx);
    cudaGetSymbolAddress((void**)&pxcat, g_xcat);
    cudaGetSymbolAddress((void**)&pgates, g_gates);

    // prep: Wcat, bsum, emb gather + zero c
    {
        int tot = 4 * Hh * (Ee + Ll + Hh) + 4 * Hh + Tt * Bb * Ee;
        prep_kernel<<<(tot + 255) / 256, 256>>>(W_ih, W_hh, b_ih, b_hh, embed_W, captions);
        zero_c_kernel<<<(Bb * Hh + 255) / 256, 256>>>();
    }

    // Initial LSTM step: gates = features @ W_ih[:, :E]^T + (b_ih + b_hh); h,c from c=0
    gemm_small(features, Ee, W_ih, Ee + Ll, pbsum,
               pgates, 4 * Hh, pgates, 4 * Hh, 4 * Hh, Bb, 4 * Hh, Ee);
    lstm_kernel<<<(Bb * Hh + 255) / 256, 256>>>();

    for (int t = 0; t < Tt; t++) {
        // assemble xq = [e_t, h]; prefill xcat(e,h), xx(h)
        assembleA_kernel<<<(Bb * (Ee + Hh) + 255) / 256, 256>>>(t);

        // prior: h @ prior_W^T + prior_b -> split (p_mu, p_sigma) directly into out
        gemm_small(ph, Hh, prior_W, Hh, prior_b,
                   out + OFF_PMU + (size_t)t * Bb * Ll, Ll,
                   out + OFF_PSIG + (size_t)t * Bb * Ll, Ll, Ll,
                   Bb, 2 * Ll, Hh);

        // qz: [e_t, h] @ qz_W^T + qz_b -> split (q_mu, q_sigma) into out
        gemm_small(pxq, Ee + Hh, qz_W, Ee + Hh, qz_b,
                   out + OFF_QMU + (size_t)t * Bb * Ll, Ll,
                   out + OFF_QSIG + (size_t)t * Bb * Ll, Ll, Ll,
                   Bb, 2 * Ll, Ee + Hh);

        // z = noise*q_sigma + q_mu -> xx[:, :L], xcat[:, E:E+L]
        z_kernel<<<(Bb * Ll + 255) / 256, 256>>>(noise, out, t);

        // logits = [z, h] @ qx_W^T + qx_b, written directly into out q_x region
        {
            float* qx_dst = out + OFF_QX + (size_t)t * Bb * Vv;
            gemm_big(pxx, Ll + Hh, qx_W, Ll + Hh, qx_b,
                     qx_dst, Vv, qx_dst, Vv, Vv, Bb, Vv, Ll + Hh);
            logsoftmax_kernel<<<Bb, 256>>>(qx_dst);
        }

        // gates = [e_t, z, h] @ [W_ih|W_hh]^T + (b_ih+b_hh)
        gemm_small(pxcat, Ee + Ll + Hh, pWcat, Ee + Ll + Hh, pbsum,
                   pgates, 4 * Hh, pgates, 4 * Hh, 4 * Hh, Bb, 4 * Hh, Ee + Ll + Hh);

        // LSTM update h, c
        lstm_kernel<<<(Bb * Hh + 255) / 256, 256>>>();
    }
}

// round 3
// speedup vs baseline: 1.2569x; 1.2569x over previous
#include <cuda_runtime.h>
#include <cuda_bf16.h>
#include <math.h>
#include <stdint.h>

// Problem constants
#define Bb 128
#define Tt 32
#define Ee 512
#define Hh 512
#define Ll 256
#define Vv 16000
#define KQX 768
#define K2 2304                 // 3 * 768 (split-bf16 folded into K)
#define NCHUNK 36               // K2 / 64
#define NTILE 125               // 16000 / 128

// Output layout (pytree leaf order): p_mus, p_sigmas, q_mus, q_sigmas, q_xs
#define OFF_PMU  ((size_t)0)
#define OFF_PSIG ((size_t)Tt * Bb * Ll)
#define OFF_QMU  ((size_t)2 * Tt * Bb * Ll)
#define OFF_QSIG ((size_t)3 * Tt * Bb * Ll)
#define OFF_QX   ((size_t)4 * Tt * Bb * Ll)

// ---------------- device scratch (static, allocation-free) ----------------
__device__ float g_emb[Tt * Bb * Ee];             // [T,B,E] gathered embeddings
__device__ float g_Wcat[4 * Hh * (Ee + Ll + Hh)]; // [2048, 1280] = [W_ih | W_hh]
__device__ float g_bsum[4 * Hh];                  // b_ih + b_hh
__device__ float g_h[Bb * Hh];
__device__ float g_c[Bb * Hh];
__device__ float g_xq[Bb * (Ee + Hh)];            // [e_t, h]   (K=1024)
__device__ float g_xcat[Bb * (Ee + Ll + Hh)];     // [e_t, z, h](K=1280)
__device__ float g_gates[Bb * 4 * Hh];            // [128, 2048]

// bf16 K-folded images for the mma.sync qx GEMM
// B image: [tile 125][chunk 36][row 128][64 bf16]
__device__ __align__(16) __nv_bfloat16 gBimg[(size_t)NTILE * NCHUNK * 128 * 64];
// A image: [chunk 36][row 128][64 bf16]
__device__ __align__(16) __nv_bfloat16 gAimg[NCHUNK * 128 * 64];

__device__ __forceinline__ float sigf(float x) { return 1.0f / (1.0f + expf(-x)); }

__device__ __forceinline__ uint32_t s2u(const void* p) {
    uint32_t a;
    asm("{ .reg .u64 t; cvta.to.shared.u64 t, %1; cvt.u32.u64 %0, t; }" : "=r"(a) : "l"(p));
    return a;
}
__device__ __forceinline__ void cpasync16(uint32_t dst, const void* src) {
    asm volatile("cp.async.cg.shared.global [%0], [%1], 16;"
                 :: "r"(dst), "l"(__cvta_generic_to_global(src)) : "memory");
}
__device__ __forceinline__ void ldmatrix_x4(uint32_t* r, uint32_t addr) {
    asm volatile("ldmatrix.sync.aligned.m8n8.x4.shared.b16 {%0,%1,%2,%3}, [%4];"
                 : "=r"(r[0]), "=r"(r[1]), "=r"(r[2]), "=r"(r[3]) : "r"(addr));
}
__device__ __forceinline__ void mma16816(float* c, const uint32_t* a, uint32_t b0, uint32_t b1) {
    asm volatile(
        "mma.sync.aligned.m16n8k16.row.col.f32.bf16.bf16.f32 "
        "{%0,%1,%2,%3}, {%4,%5,%6,%7}, {%8,%9}, {%0,%1,%2,%3};"
        : "+f"(c[0]), "+f"(c[1]), "+f"(c[2]), "+f"(c[3])
        : "r"(a[0]), "r"(a[1]), "r"(a[2]), "r"(a[3]), "r"(b0), "r"(b1));
}

// ---------------- prep: Wcat, bsum, embedding gather ----------------
__global__ void prep_kernel(const float* __restrict__ W_ih, const float* __restrict__ W_hh,
                            const float* __restrict__ b_ih, const float* __restrict__ b_hh,
                            const float* __restrict__ embed_W, const int* __restrict__ captions) {
    const int N_WCAT = 4 * Hh * (Ee + Ll + Hh);   // 2048*1280
    const int N_BS = 4 * Hh;
    const int N_EMB = Tt * Bb * Ee;
    int idx = blockIdx.x * blockDim.x + threadIdx.x;
    if (idx < N_WCAT) {
        int n = idx / (Ee + Ll + Hh);
        int k = idx % (Ee + Ll + Hh);
        float v = (k < Ee + Ll) ? W_ih[n * (Ee + Ll) + k] : W_hh[n * Hh + (k - (Ee + Ll))];
        g_Wcat[idx] = v;
    } else if (idx < N_WCAT + N_BS) {
        int n = idx - N_WCAT;
        g_bsum[n] = b_ih[n] + b_hh[n];
    } else if (idx < N_WCAT + N_BS + N_EMB) {
        int j = idx - N_WCAT - N_BS;
        int tb = j / Ee;
        int e = j % Ee;
        int t = tb / Bb, b = tb % Bb;
        int cap = captions[b * Tt + t];
        g_emb[j] = embed_W[(size_t)cap * Ee + e];
    }
}

__global__ void zero_c_kernel() {
    int idx = blockIdx.x * blockDim.x + threadIdx.x;
    if (idx < Bb * Hh) g_c[idx] = 0.0f;
}

// Build the split-bf16 K-folded image of qx_W.
// Segment p of K2: p=0 -> Bh, p=1 -> Bl, p=2 -> Bh  (paired with A: Ah, Ah, Al)
__global__ void prep_qx_kernel(const float* __restrict__ qx_W) {
    size_t idx = (size_t)blockIdx.x * blockDim.x + threadIdx.x;
    if (idx >= (size_t)Vv * K2) return;
    int n = (int)(idx / K2);
    int k2 = (int)(idx - (size_t)n * K2);
    int p = k2 / KQX;
    int k = k2 - p * KQX;
    float v = qx_W[(size_t)n * KQX + k];
    __nv_bfloat16 hi = __float2bfloat16(v);
    float lo_f = v - __bfloat162float(hi);
    __nv_bfloat16 val = (p == 1) ? __float2bfloat16(lo_f) : hi;
    int tile = n >> 7, row = n & 127;
    int chunk = k2 >> 6, kk = k2 & 63;
    gBimg[(((size_t)tile * NCHUNK + chunk) * 128 + row) * 64 + kk] = val;
}

// ---------------- fp32 SGEMM for the small matmuls ----------------
template <int BM, int BN, int BK, int TM, int TN>
__global__ void sgemm_bt(const float* __restrict__ A, int lda,
                         const float* __restrict__ Bw, int ldb,
                         const float* __restrict__ bias,
                         float* __restrict__ C0, int ldc0,
                         float* __restrict__ C1, int ldc1, int splitN,
                         int M, int N, int K) {
    constexpr int THREADS = (BM / TM) * (BN / TN);
    __shared__ float As[BK][BM];
    __shared__ float Bs[BK][BN];
    const int tid = threadIdx.x;
    const int block_m = blockIdx.x * BM;
    const int block_n = blockIdx.y * BN;
    const int tn_ = tid % (BN / TN);
    const int tm_ = tid / (BN / TN);

    float acc[TM][TN];
#pragma unroll
    for (int i = 0; i < TM; i++)
#pragma unroll
        for (int j = 0; j < TN; j++) acc[i][j] = 0.0f;

    constexpr int A_F4 = BM * BK / 4;
    constexpr int B_F4 = BN * BK / 4;

    for (int k0 = 0; k0 < K; k0 += BK) {
#pragma unroll
        for (int i = tid; i < A_F4; i += THREADS) {
            int row = i / (BK / 4);
            int kq = i % (BK / 4);
            float4 v = *(const float4*)(A + (size_t)(block_m + row) * lda + k0 + kq * 4);
            As[kq * 4 + 0][row] = v.x;
            As[kq * 4 + 1][row] = v.y;
            As[kq * 4 + 2][row] = v.z;
            As[kq * 4 + 3][row] = v.w;
        }
#pragma unroll
        for (int i = tid; i < B_F4; i += THREADS) {
            int row = i / (BK / 4);
            int kq = i % (BK / 4);
            float4 v = *(const float4*)(Bw + (size_t)(block_n + row) * ldb + k0 + kq * 4);
            Bs[kq * 4 + 0][row] = v.x;
            Bs[kq * 4 + 1][row] = v.y;
            Bs[kq * 4 + 2][row] = v.z;
            Bs[kq * 4 + 3][row] = v.w;
        }
        __syncthreads();
#pragma unroll
        for (int kk = 0; kk < BK; kk++) {
            float ra[TM], rb[TN];
#pragma unroll
            for (int i = 0; i < TM; i++) ra[i] = As[kk][tm_ * TM + i];
#pragma unroll
            for (int j = 0; j < TN; j++) rb[j] = Bs[kk][tn_ * TN + j];
#pragma unroll
            for (int i = 0; i < TM; i++)
#pragma unroll
                for (int j = 0; j < TN; j++) acc[i][j] = fmaf(ra[i], rb[j], acc[i][j]);
        }
        __syncthreads();
    }

#pragma unroll
    for (int i = 0; i < TM; i++) {
        int m = block_m + tm_ * TM + i;
#pragma unroll
        for (int j = 0; j < TN; j++) {
            int n = block_n + tn_ * TN + j;
            float v = acc[i][j] + bias[n];
            if (n < splitN)
                C0[(size_t)m * ldc0 + n] = v;
            else
                C1[(size_t)m * ldc1 + (n - splitN)] = v;
        }
    }
}

// ---------------- per-step elementwise kernels ----------------
__global__ void assembleA_kernel(int t) {
    int idx = blockIdx.x * blockDim.x + threadIdx.x;
    if (idx >= Bb * (Ee + Hh)) return;
    int b = idx / (Ee + Hh);
    int k = idx % (Ee + Hh);
    float v;
    if (k < Ee) {
        v = g_emb[((size_t)t * Bb + b) * Ee + k];
        g_xcat[b * (Ee + Ll + Hh) + k] = v;
    } else {
        int kh = k - Ee;
        v = g_h[b * Hh + kh];
        g_xcat[b * (Ee + Ll + Hh) + Ee + Ll + kh] = v;
    }
    g_xq[idx] = v;
}

// Fused: compute z (reparameterize) / pick h, write z into xcat, and build the
// split-bf16 K-folded A image.  Segment p: p=0,1 -> Ah; p=2 -> Al.
__global__ void aimgz_kernel(const float* __restrict__ noise, const float* __restrict__ out, int t) {
    int idx = blockIdx.x * blockDim.x + threadIdx.x;
    if (idx >= Bb * K2) return;
    int m = idx / K2;
    int k2 = idx - m * K2;
    int p = k2 / KQX;
    int k = k2 - p * KQX;
    float v;
    if (k < Ll) {
        size_t o = ((size_t)t * Bb + m) * Ll + k;
        float qm = out[OFF_QMU + o];
        float qs = out[OFF_QSIG + o];
        v = noise[((size_t)m * Tt + t) * Ll + k] * qs + qm;
        if (p == 0) g_xcat[m * (Ee + Ll + Hh) + Ee + k] = v;
    } else {
        v = g_h[m * Hh + (k - Ll)];
    }
    __nv_bfloat16 hi = __float2bfloat16(v);
    __nv_bfloat16 val = (p == 2) ? __float2bfloat16(v - __bfloat162float(hi)) : hi;
    int chunk = k2 >> 6, kk = k2 & 63;
    gAimg[((size_t)chunk * 128 + m) * 64 + kk] = val;
}

// LSTM elementwise update from g_gates (PyTorch gate order i,f,g,o)
__global__ void lstm_kernel() {
    int idx = blockIdx.x * blockDim.x + threadIdx.x;
    if (idx >= Bb * Hh) return;
    int b = idx / Hh, n = idx % Hh;
    const float* gr = g_gates + (size_t)b * 4 * Hh;
    float gi = gr[n];
    float gf = gr[Hh + n];
    float gg = gr[2 * Hh + n];
    float go = gr[3 * Hh + n];
    float c = sigf(gf) * g_c[idx] + sigf(gi) * tanhf(gg);
    g_c[idx] = c;
    g_h[idx] = sigf(go) * tanhf(c);
}

// ---------------- mma.sync qx GEMM: logits = [z,h] @ qx_W^T + qx_b ----------------
// grid = 125 CTAs (128x128 tile each), 256 threads (8 warps, each 64x32).
// smem: 2 stages x (A 128x144B + B 128x144B) = 73728 B, row pitch 144B (pad).
#define PITCH 144
#define STAGE_B 18432          // 128 * 144
#define STAGE_SZ 36864

__global__ void __launch_bounds__(256) qx_mma_kernel(const float* __restrict__ qx_b,
                                                     float* __restrict__ dst) {
    extern __shared__ __align__(16) char smem[];
    const uint32_t sb = s2u(smem);
    const int tid = threadIdx.x;
    const int wid = tid >> 5;
    const int lane = tid & 31;
    const int warp_m = wid >> 2;          // 0..1  -> 64 rows
    const int warp_n = wid & 3;           // 0..3  -> 32 cols
    const int n0 = blockIdx.x << 7;

    const char* gA = (const char*)gAimg;
    const char* gB = (const char*)gBimg + (size_t)blockIdx.x * ((size_t)NCHUNK * 128 * 64 * 2);

    float acc[4][4][4];
#pragma unroll
    for (int i = 0; i < 4; i++)
#pragma unroll
        for (int j = 0; j < 4; j++)
#pragma unroll
            for (int q = 0; q < 4; q++) acc[i][j][q] = 0.0f;

    // ldmatrix per-lane address components
    const int a_row = lane & 15;                 // row within 16
    const int a_coff = (lane >> 4) << 4;         // 0 or 16 bytes (k cols 0..7 / 8..15)
    const int b_row = ((lane >> 4) << 3) | (lane & 7);
    const int b_coff = ((lane >> 3) & 1) << 4;

    // prefetch stages 0,1
#pragma unroll
    for (int s = 0; s < 2; s++) {
        const char* srcA = gA + (size_t)s * 16384;
        const char* srcB = gB + (size_t)s * 16384;
        uint32_t st = sb + s * STAGE_SZ;
#pragma unroll
        for (int j = 0; j < 4; j++) {
            int i = tid + j * 256;
            int r = i >> 3, q = i & 7;
            cpasync16(st + r * PITCH + q * 16, srcA + r * 128 + q * 16);
        }
#pragma unroll
        for (int j = 0; j < 4; j++) {
            int i = tid + j * 256;
            int r = i >> 3, q = i & 7;
            cpasync16(st + STAGE_B + r * PITCH + q * 16, srcB + r * 128 + q * 16);
        }
        asm volatile("cp.async.commit_group;" ::: "memory");
    }

    for (int c = 0; c < NCHUNK; c++) {
        if (c < NCHUNK - 2)
            asm volatile("cp.async.wait_group 1;" ::: "memory");
        else
            asm volatile("cp.async.wait_group 0;" ::: "memory");
        __syncthreads();

        const uint32_t stg = sb + (c & 1) * STAGE_SZ;
        const uint32_t As = stg;
        const uint32_t Bs = stg + STAGE_B;
#pragma unroll
        for (int ks = 0; ks < 4; ks++) {
            uint32_t a[4][4];
#pragma unroll
            for (int mi = 0; mi < 4; mi++) {
                uint32_t addr = As + (uint32_t)(warp_m * 64 + mi * 16 + a_row) * PITCH +
                                ks * 32 + a_coff;
                ldmatrix_x4(a[mi], addr);
            }
#pragma unroll
            for (int jp = 0; jp < 2; jp++) {
                uint32_t b[4];
                uint32_t addr = Bs + (uint32_t)(warp_n * 32 + jp * 16 + b_row) * PITCH +
                                ks * 32 + b_coff;
                ldmatrix_x4(b, addr);
#pragma unroll
                for (int mi = 0; mi < 4; mi++) {
                    mma16816(acc[mi][jp * 2 + 0], a[mi], b[0], b[1]);
                    mma16816(acc[mi][jp * 2 + 1], a[mi], b[2], b[3]);
                }
            }
        }
        __syncthreads();
        if (c + 2 < NCHUNK) {
            const char* srcA = gA + (size_t)(c + 2) * 16384;
            const char* srcB = gB + (size_t)(c + 2) * 16384;
            uint32_t st = sb + (c & 1) * STAGE_SZ;
#pragma unroll
            for (int j = 0; j < 4; j++) {
                int i = tid + j * 256;
                int r = i >> 3, q = i & 7;
                cpasync16(st + r * PITCH + q * 16, srcA + r * 128 + q * 16);
            }
#pragma unroll
            for (int j = 0; j < 4; j++) {
                int i = tid + j * 256;
                int r = i >> 3, q = i & 7;
                cpasync16(st + STAGE_B + r * PITCH + q * 16, srcB + r * 128 + q * 16);
            }
        }
        asm volatile("cp.async.commit_group;" ::: "memory");
    }

    // Epilogue: add bias, write fp32 logits
    const int g = lane >> 2, tq = lane & 3;
#pragma unroll
    for (int mi = 0; mi < 4; mi++) {
        int row = warp_m * 64 + mi * 16 + g;
#pragma unroll
        for (int nj = 0; nj < 4; nj++) {
            int col = n0 + warp_n * 32 + nj * 8 + 2 * tq;
            float b0 = qx_b[col], b1 = qx_b[col + 1];
            float2 v0 = make_float2(acc[mi][nj][0] + b0, acc[mi][nj][1] + b1);
            float2 v1 = make_float2(acc[mi][nj][2] + b0, acc[mi][nj][3] + b1);
            *(float2*)(dst + (size_t)row * Vv + col) = v0;
            *(float2*)(dst + (size_t)(row + 8) * Vv + col) = v1;
        }
    }
}

// In-place log_softmax over rows of length V (one block per row)
__global__ void logsoftmax_kernel(float* __restrict__ base) {
    float* x = base + (size_t)blockIdx.x * Vv;
    __shared__ float sred[32];
    __shared__ float sval;
    const int tid = threadIdx.x;

    float m = -3.4e38f;
    for (int i = tid; i < Vv; i += 256) m = fmaxf(m, x[i]);
#pragma unroll
    for (int o = 16; o; o >>= 1) m = fmaxf(m, __shfl_xor_sync(0xffffffffu, m, o));
    if ((tid & 31) == 0) sred[tid >> 5] = m;
    __syncthreads();
    if (tid < 32) {
        float v = (tid < 8) ? sred[tid] : -3.4e38f;
#pragma unroll
        for (int o = 4; o; o >>= 1) v = fmaxf(v, __shfl_xor_sync(0xffffffffu, v, o));
        if (tid == 0) sval = v;
    }
    __syncthreads();
    m = sval;

    float s = 0.0f;
    for (int i = tid; i < Vv; i += 256) s += expf(x[i] - m);
#pragma unroll
    for (int o = 16; o; o >>= 1) s += __shfl_xor_sync(0xffffffffu, s, o);
    __syncthreads();
    if ((tid & 31) == 0) sred[tid >> 5] = s;
    __syncthreads();
    if (tid < 32) {
        float v = (tid < 8) ? sred[tid] : 0.0f;
#pragma unroll
        for (int o = 4; o; o >>= 1) v += __shfl_xor_sync(0xffffffffu, v, o);
        if (tid == 0) sval = m + logf(v);
    }
    __syncthreads();
    float lz = sval;
    for (int i = tid; i < Vv; i += 256) x[i] -= lz;
}

// ---------------- host-side launch helpers ----------------
static inline void gemm_small(const float* A, int lda, const float* Bw, int ldb, const float* bias,
                              float* C0, int ldc0, float* C1, int ldc1, int splitN,
                              int M, int N, int K) {
    dim3 grid(M / 32, N / 64);
    sgemm_bt<32, 64, 8, 4, 4><<<grid, 128>>>(A, lda, Bw, ldb, bias, C0, ldc0, C1, ldc1, splitN, M, N, K);
}

extern "C" void kernel_launch(void* const* d_in, const int* in_sizes, int n_in,
                              void* d_out, int out_size) {
    const float* features = (const float*)d_in[0];
    const int* captions = (const int*)d_in[1];
    // d_in[2] lengths: unused (all == T)
    const float* noise   = (const float*)d_in[3];
    const float* embed_W = (const float*)d_in[4];
    const float* W_ih    = (const float*)d_in[5];
    const float* W_hh    = (const float*)d_in[6];
    const float* b_ih    = (const float*)d_in[7];
    const float* b_hh    = (const float*)d_in[8];
    const float* qz_W    = (const float*)d_in[9];
    const float* qz_b    = (const float*)d_in[10];
    const float* prior_W = (const float*)d_in[11];
    const float* prior_b = (const float*)d_in[12];
    const float* qx_W    = (const float*)d_in[13];
    const float* qx_b    = (const float*)d_in[14];
    float* out = (float*)d_out;

    float *pWcat, *pbsum, *ph, *pxq, *pxcat, *pgates;
    cudaGetSymbolAddress((void**)&pWcat, g_Wcat);
    cudaGetSymbolAddress((void**)&pbsum, g_bsum);
    cudaGetSymbolAddress((void**)&ph, g_h);
    cudaGetSymbolAddress((void**)&pxq, g_xq);
    cudaGetSymbolAddress((void**)&pxcat, g_xcat);
    cudaGetSymbolAddress((void**)&pgates, g_gates);

    cudaFuncSetAttribute(qx_mma_kernel, cudaFuncAttributeMaxDynamicSharedMemorySize, 2 * STAGE_SZ);

    // prep: Wcat, bsum, emb gather, zero c, split-bf16 B-image
    {
        int tot = 4 * Hh * (Ee + Ll + Hh) + 4 * Hh + Tt * Bb * Ee;
        prep_kernel<<<(tot + 255) / 256, 256>>>(W_ih, W_hh, b_ih, b_hh, embed_W, captions);
        zero_c_kernel<<<(Bb * Hh + 255) / 256, 256>>>();
        size_t totq = (size_t)Vv * K2;
        prep_qx_kernel<<<(int)((totq + 255) / 256), 256>>>(qx_W);
    }

    // Initial LSTM step: gates = features @ W_ih[:, :E]^T + (b_ih + b_hh); h,c from c=0
    gemm_small(features, Ee, W_ih, Ee + Ll, pbsum,
               pgates, 4 * Hh, pgates, 4 * Hh, 4 * Hh, Bb, 4 * Hh, Ee);
    lstm_kernel<<<(Bb * Hh + 255) / 256, 256>>>();

    for (int t = 0; t < Tt; t++) {
        assembleA_kernel<<<(Bb * (Ee + Hh) + 255) / 256, 256>>>(t);

        // prior: h @ prior_W^T + prior_b -> split (p_mu, p_sigma)
        gemm_small(ph, Hh, prior_W, Hh, prior_b,
                   out + OFF_PMU + (size_t)t * Bb * Ll, Ll,
                   out + OFF_PSIG + (size_t)t * Bb * Ll, Ll, Ll,
                   Bb, 2 * Ll, Hh);

        // qz: [e_t, h] @ qz_W^T + qz_b -> split (q_mu, q_sigma)
        gemm_small(pxq, Ee + Hh, qz_W, Ee + Hh, qz_b,
                   out + OFF_QMU + (size_t)t * Bb * Ll, Ll,
                   out + OFF_QSIG + (size_t)t * Bb * Ll, Ll, Ll,
                   Bb, 2 * Ll, Ee + Hh);

        // z + split-bf16 A-image (fused)
        aimgz_kernel<<<(Bb * K2 + 255) / 256, 256>>>(noise, out, t);

        // logits via mma.sync split-bf16, then log-softmax
        {
            float* qx_dst = out + OFF_QX + (size_t)t * Bb * Vv;
            qx_mma_kernel<<<NTILE, 256, 2 * STAGE_SZ>>>(qx_b, qx_dst);
            logsoftmax_kernel<<<Bb, 256>>>(qx_dst);
        }

        // gates = [e_t, z, h] @ [W_ih|W_hh]^T + (b_ih+b_hh)
        gemm_small(pxcat, Ee + Ll + Hh, pWcat, Ee + Ll + Hh, pbsum,
                   pgates, 4 * Hh, pgates, 4 * Hh, 4 * Hh, Bb, 4 * Hh, Ee + Ll + Hh);

        lstm_kernel<<<(Bb * Hh + 255) / 256, 256>>>();
    }
}

// round 4
// speedup vs baseline: 2.0109x; 1.5998x over previous
#include <cuda_runtime.h>
#include <cuda_bf16.h>
#include <math.h>
#include <stdint.h>

// Problem constants
#define Bb 128
#define Tt 32
#define Ee 512
#define Hh 512
#define Ll 256
#define Vv 16000

// K2 (split-bf16 folded K) per GEMM
#define NCH_G  60      // gates: K=1280 -> 3840
#define NCH_PQ 48      // prior+qz: K=1024 -> 3072
#define NCH_QX 36      // qx: K=768 -> 2304
#define NT_G   16      // gates N tiles (2048/128)
#define NT_PQ  8       // pq N tiles (1024/128)
#define NT_QX  125     // qx N tiles (16000/128)

// Output layout (pytree leaf order): p_mus, p_sigmas, q_mus, q_sigmas, q_xs
#define OFF_PMU  ((size_t)0)
#define OFF_PSIG ((size_t)Tt * Bb * Ll)
#define OFF_QMU  ((size_t)2 * Tt * Bb * Ll)
#define OFF_QSIG ((size_t)3 * Tt * Bb * Ll)
#define OFF_QX   ((size_t)4 * Tt * Bb * Ll)

// ---------------- device scratch (static, allocation-free) ----------------
__device__ float g_emb[Tt * Bb * Ee];          // [T,B,E]
__device__ float g_bsum[4 * Hh];               // b_ih + b_hh
__device__ float g_bias_pq[1024];              // [qz_b | prior_b]
__device__ float g_h[Bb * Hh];
__device__ float g_c[Bb * Hh];
__device__ float g_gates[Bb * 4 * Hh];

// Weight images (built once): [tile][chunk][row 128][64] bf16
__device__ __align__(16) __nv_bfloat16 gBg[(size_t)NT_G * NCH_G * 8192];
__device__ __align__(16) __nv_bfloat16 gBpq[(size_t)NT_PQ * NCH_PQ * 8192];
__device__ __align__(16) __nv_bfloat16 gBqx[(size_t)NT_QX * NCH_QX * 8192];
// A images (rebuilt per step): [chunk][row 128][64]
__device__ __align__(16) __nv_bfloat16 gAg[NCH_G * 8192];
__device__ __align__(16) __nv_bfloat16 gApq[NCH_PQ * 8192];
__device__ __align__(16) __nv_bfloat16 gAqx[NCH_QX * 8192];

__device__ __forceinline__ float sigf(float x) { return 1.0f / (1.0f + expf(-x)); }

__device__ __forceinline__ uint32_t s2u(const void* p) {
    uint32_t a;
    asm("{ .reg .u64 t; cvta.to.shared.u64 t, %1; cvt.u32.u64 %0, t; }" : "=r"(a) : "l"(p));
    return a;
}
__device__ __forceinline__ void cpasync16(uint32_t dst, const void* src) {
    asm volatile("cp.async.cg.shared.global [%0], [%1], 16;"
                 :: "r"(dst), "l"(__cvta_generic_to_global(src)) : "memory");
}
__device__ __forceinline__ void ldmatrix_x4(uint32_t* r, uint32_t addr) {
    asm volatile("ldmatrix.sync.aligned.m8n8.x4.shared.b16 {%0,%1,%2,%3}, [%4];"
                 : "=r"(r[0]), "=r"(r[1]), "=r"(r[2]), "=r"(r[3]) : "r"(addr));
}
__device__ __forceinline__ void mma16816(float* c, const uint32_t* a, uint32_t b0, uint32_t b1) {
    asm volatile(
        "mma.sync.aligned.m16n8k16.row.col.f32.bf16.bf16.f32 "
        "{%0,%1,%2,%3}, {%4,%5,%6,%7}, {%8,%9}, {%0,%1,%2,%3};"
        : "+f"(c[0]), "+f"(c[1]), "+f"(c[2]), "+f"(c[3])
        : "r"(a[0]), "r"(a[1]), "r"(a[2]), "r"(a[3]), "r"(b0), "r"(b1));
}
// image element position: ((k2>>6)*128 + m)*64 + (k2&63)
__device__ __forceinline__ size_t ipos(int k2, int m) {
    return (((size_t)(k2 >> 6) * 128 + m) << 6) + (k2 & 63);
}

// ---------------- one-time prep kernels ----------------
__global__ void prep_misc_kernel(const float* __restrict__ b_ih, const float* __restrict__ b_hh,
                                 const float* __restrict__ qz_b, const float* __restrict__ prior_b,
                                 const float* __restrict__ embed_W, const int* __restrict__ captions) {
    int idx = blockIdx.x * blockDim.x + threadIdx.x;
    const int N_EMB = Tt * Bb * Ee;
    if (idx < N_EMB) {
        int tb = idx / Ee;
        int e = idx % Ee;
        int t = tb / Bb, b = tb % Bb;
        g_emb[idx] = embed_W[(size_t)captions[b * Tt + t] * Ee + e];
    } else if (idx < N_EMB + 4 * Hh) {
        int n = idx - N_EMB;
        g_bsum[n] = b_ih[n] + b_hh[n];
    } else if (idx < N_EMB + 4 * Hh + 1024) {
        int n = idx - N_EMB - 4 * Hh;
        g_bias_pq[n] = (n < 512) ? qz_b[n] : prior_b[n - 512];
    } else if (idx < N_EMB + 4 * Hh + 1024 + Bb * Hh) {
        g_c[idx - N_EMB - 4 * Hh - 1024] = 0.0f;
    }
}

// gates weight image: N=2048, K order [e(512), z(256), h(512)]; fold B=[hi|lo|hi]
__global__ void prep_wg_kernel(const float* __restrict__ W_ih, const float* __restrict__ W_hh) {
    size_t idx = (size_t)blockIdx.x * blockDim.x + threadIdx.x;
    if (idx >= (size_t)2048 * 3840) return;
    int n = (int)(idx / 3840);
    int k2 = (int)(idx - (size_t)n * 3840);
    int p = k2 / 1280, k = k2 - p * 1280;
    float v = (k < 768) ? W_ih[(size_t)n * 768 + k] : W_hh[(size_t)n * 512 + (k - 768)];
    __nv_bfloat16 hi = __float2bfloat16(v);
    __nv_bfloat16 val = (p == 1) ? __float2bfloat16(v - __bfloat162float(hi)) : hi;
    int tile = n >> 7, row = n & 127;
    gBg[((size_t)tile * NCH_G * 8192) + ((size_t)(k2 >> 6) * 128 + row) * 64 + (k2 & 63)] = val;
}

// pq weight image: N=1024 (qz rows 0-511, prior rows 512-1023 padded over e), K order [e, h]
__global__ void prep_wpq_kernel(const float* __restrict__ qz_W, const float* __restrict__ prior_W) {
    size_t idx = (size_t)blockIdx.x * blockDim.x + threadIdx.x;
    if (idx >= (size_t)1024 * 3072) return;
    int n = (int)(idx / 3072);
    int k2 = (int)(idx - (size_t)n * 3072);
    int p = k2 / 1024, k = k2 - p * 1024;
    float v;
    if (n < 512) v = qz_W[(size_t)n * 1024 + k];
    else v = (k < 512) ? 0.0f : prior_W[(size_t)(n - 512) * 512 + (k - 512)];
    __nv_bfloat16 hi = __float2bfloat16(v);
    __nv_bfloat16 val = (p == 1) ? __float2bfloat16(v - __bfloat162float(hi)) : hi;
    int tile = n >> 7, row = n & 127;
    gBpq[((size_t)tile * NCH_PQ * 8192) + ((size_t)(k2 >> 6) * 128 + row) * 64 + (k2 & 63)] = val;
}

// qx weight image: N=16000, K order [z(256), h(512)]
__global__ void prep_wqx_kernel(const float* __restrict__ qx_W) {
    size_t idx = (size_t)blockIdx.x * blockDim.x + threadIdx.x;
    if (idx >= (size_t)Vv * 2304) return;
    int n = (int)(idx / 2304);
    int k2 = (int)(idx - (size_t)n * 2304);
    int p = k2 / 768, k = k2 - p * 768;
    float v = qx_W[(size_t)n * 768 + k];
    __nv_bfloat16 hi = __float2bfloat16(v);
    __nv_bfloat16 val = (p == 1) ? __float2bfloat16(v - __bfloat162float(hi)) : hi;
    int tile = n >> 7, row = n & 127;
    gBqx[((size_t)tile * NCH_QX * 8192) + ((size_t)(k2 >> 6) * 128 + row) * 64 + (k2 & 63)] = val;
}

// ---------------- fp32 SGEMM (initial step only) ----------------
template <int BM, int BN, int BK, int TM, int TN>
__global__ void sgemm_bt(const float* __restrict__ A, int lda,
                         const float* __restrict__ Bw, int ldb,
                         const float* __restrict__ bias,
                         float* __restrict__ C0, int ldc0, int M, int N, int K) {
    constexpr int THREADS = (BM / TM) * (BN / TN);
    __shared__ float As[BK][BM];
    __shared__ float Bs[BK][BN];
    const int tid = threadIdx.x;
    const int block_m = blockIdx.x * BM;
    const int block_n = blockIdx.y * BN;
    const int tn_ = tid % (BN / TN);
    const int tm_ = tid / (BN / TN);

    float acc[TM][TN];
#pragma unroll
    for (int i = 0; i < TM; i++)
#pragma unroll
        for (int j = 0; j < TN; j++) acc[i][j] = 0.0f;

    constexpr int A_F4 = BM * BK / 4;
    constexpr int B_F4 = BN * BK / 4;

    for (int k0 = 0; k0 < K; k0 += BK) {
#pragma unroll
        for (int i = tid; i < A_F4; i += THREADS) {
            int row = i / (BK / 4), kq = i % (BK / 4);
            float4 v = *(const float4*)(A + (size_t)(block_m + row) * lda + k0 + kq * 4);
            As[kq * 4 + 0][row] = v.x; As[kq * 4 + 1][row] = v.y;
            As[kq * 4 + 2][row] = v.z; As[kq * 4 + 3][row] = v.w;
        }
#pragma unroll
        for (int i = tid; i < B_F4; i += THREADS) {
            int row = i / (BK / 4), kq = i % (BK / 4);
            float4 v = *(const float4*)(Bw + (size_t)(block_n + row) * ldb + k0 + kq * 4);
            Bs[kq * 4 + 0][row] = v.x; Bs[kq * 4 + 1][row] = v.y;
            Bs[kq * 4 + 2][row] = v.z; Bs[kq * 4 + 3][row] = v.w;
        }
        __syncthreads();
#pragma unroll
        for (int kk = 0; kk < BK; kk++) {
            float ra[TM], rb[TN];
#pragma unroll
            for (int i = 0; i < TM; i++) ra[i] = As[kk][tm_ * TM + i];
#pragma unroll
            for (int j = 0; j < TN; j++) rb[j] = Bs[kk][tn_ * TN + j];
#pragma unroll
            for (int i = 0; i < TM; i++)
#pragma unroll
                for (int j = 0; j < TN; j++) acc[i][j] = fmaf(ra[i], rb[j], acc[i][j]);
        }
        __syncthreads();
    }
#pragma unroll
    for (int i = 0; i < TM; i++) {
        int m = block_m + tm_ * TM + i;
#pragma unroll
        for (int j = 0; j < TN; j++) {
            int n = block_n + tn_ * TN + j;
            C0[(size_t)m * ldc0 + n] = acc[i][j] + bias[n];
        }
    }
}

// ---------------- per-step A-image builders ----------------
// builder1: e and h sections of all three A images (runs before pq GEMM)
__global__ void build1_kernel(int t) {
    int idx = blockIdx.x * blockDim.x + threadIdx.x;
    if (idx >= Bb * 1024) return;
    int m = idx >> 10;
    int k = idx & 1023;                      // K order [e(512), h(512)]
    float v = (k < 512) ? g_emb[((size_t)t * Bb + m) * Ee + k] : g_h[m * Hh + (k - 512)];
    __nv_bfloat16 hi = __float2bfloat16(v);
    __nv_bfloat16 lo = __float2bfloat16(v - __bfloat162float(hi));
    // pq A (K=1024, fold A=[hi|hi|lo])
    gApq[ipos(k, m)] = hi;
    gApq[ipos(k + 1024, m)] = hi;
    gApq[ipos(k + 2048, m)] = lo;
    // gates A (K order [e, z, h], K=1280)
    int kg = (k < 512) ? k : (k + 256);
    gAg[ipos(kg, m)] = hi;
    gAg[ipos(kg + 1280, m)] = hi;
    gAg[ipos(kg + 2560, m)] = lo;
    // qx A (K order [z, h], K=768): only h
    if (k >= 512) {
        int kq = k - 256;                    // 256..767
        gAqx[ipos(kq, m)] = hi;
        gAqx[ipos(kq + 768, m)] = hi;
        gAqx[ipos(kq + 1536, m)] = lo;
    }
}

// builder2: z = noise * q_sigma + q_mu -> z sections of gates/qx A images
__global__ void build2_kernel(const float* __restrict__ noise, const float* __restrict__ out, int t) {
    int idx = blockIdx.x * blockDim.x + threadIdx.x;
    if (idx >= Bb * Ll) return;
    int m = idx >> 8;
    int l = idx & 255;
    size_t o = ((size_t)t * Bb + m) * Ll + l;
    float v = noise[((size_t)m * Tt + t) * Ll + l] * out[OFF_QSIG + o] + out[OFF_QMU + o];
    __nv_bfloat16 hi = __float2bfloat16(v);
    __nv_bfloat16 lo = __float2bfloat16(v - __bfloat162float(hi));
    int kg = 512 + l;
    gAg[ipos(kg, m)] = hi;
    gAg[ipos(kg + 1280, m)] = hi;
    gAg[ipos(kg + 2560, m)] = lo;
    gAqx[ipos(l, m)] = hi;
    gAqx[ipos(l + 768, m)] = hi;
    gAqx[ipos(l + 1536, m)] = lo;
}

// LSTM elementwise update (PyTorch gate order i,f,g,o)
__global__ void lstm_kernel() {
    int idx = blockIdx.x * blockDim.x + threadIdx.x;
    if (idx >= Bb * Hh) return;
    int b = idx / Hh, n = idx % Hh;
    const float* gr = g_gates + (size_t)b * 4 * Hh;
    float gi = gr[n], gf = gr[Hh + n], gg = gr[2 * Hh + n], go = gr[3 * Hh + n];
    float c = sigf(gf) * g_c[idx] + sigf(gi) * tanhf(gg);
    g_c[idx] = c;
    g_h[idx] = sigf(go) * tanhf(c);
}

// ---------------- generic split-bf16 mma GEMM ----------------
// grid = ntiles CTAs (128x128 tile), 256 threads (8 warps of 64x32)
// MODE 0: dst[row*ldc + col] = acc + bias[col]
// MODE 1: 4-way column split (256 each) into dst,d1,d2,d3 with row stride 256
#define PITCH 144
#define STAGE_B 18432
#define STAGE_SZ 36864

template <int MODE>
__global__ void __launch_bounds__(256) tc_gemm(
    const __nv_bfloat16* __restrict__ Aimg, const __nv_bfloat16* __restrict__ Bimg,
    int nchunk, const float* __restrict__ bias,
    float* __restrict__ dst, int ldc,
    float* __restrict__ d1, float* __restrict__ d2, float* __restrict__ d3) {
    extern __shared__ __align__(16) char smem[];
    const uint32_t sb = s2u(smem);
    const int tid = threadIdx.x;
    const int wid = tid >> 5;
    const int lane = tid & 31;
    const int warp_m = wid >> 2;
    const int warp_n = wid & 3;
    const int n0 = blockIdx.x << 7;

    const char* gA = (const char*)Aimg;
    const char* gB = (const char*)Bimg + (size_t)blockIdx.x * ((size_t)nchunk * 16384);

    float acc[4][4][4];
#pragma unroll
    for (int i = 0; i < 4; i++)
#pragma unroll
        for (int j = 0; j < 4; j++)
#pragma unroll
            for (int q = 0; q < 4; q++) acc[i][j][q] = 0.0f;

    const int a_row = lane & 15;
    const int a_coff = (lane >> 4) << 4;
    const int b_row = ((lane >> 4) << 3) | (lane & 7);
    const int b_coff = ((lane >> 3) & 1) << 4;

#pragma unroll
    for (int s = 0; s < 2; s++) {
        const char* srcA = gA + (size_t)s * 16384;
        const char* srcB = gB + (size_t)s * 16384;
        uint32_t st = sb + s * STAGE_SZ;
#pragma unroll
        for (int j = 0; j < 4; j++) {
            int i = tid + j * 256;
            int r = i >> 3, q = i & 7;
            cpasync16(st + r * PITCH + q * 16, srcA + r * 128 + q * 16);
        }
#pragma unroll
        for (int j = 0; j < 4; j++) {
            int i = tid + j * 256;
            int r = i >> 3, q = i & 7;
            cpasync16(st + STAGE_B + r * PITCH + q * 16, srcB + r * 128 + q * 16);
        }
        asm volatile("cp.async.commit_group;" ::: "memory");
    }

    for (int c = 0; c < nchunk; c++) {
        if (c < nchunk - 2)
            asm volatile("cp.async.wait_group 1;" ::: "memory");
        else
            asm volatile("cp.async.wait_group 0;" ::: "memory");
        __syncthreads();

        const uint32_t stg = sb + (c & 1) * STAGE_SZ;
        const uint32_t As = stg;
        const uint32_t Bs = stg + STAGE_B;
#pragma unroll
        for (int ks = 0; ks < 4; ks++) {
            uint32_t a[4][4];
#pragma unroll
            for (int mi = 0; mi < 4; mi++) {
                uint32_t addr = As + (uint32_t)(warp_m * 64 + mi * 16 + a_row) * PITCH +
                                ks * 32 + a_coff;
                ldmatrix_x4(a[mi], addr);
            }
#pragma unroll
            for (int jp = 0; jp < 2; jp++) {
                uint32_t b[4];
                uint32_t addr = Bs + (uint32_t)(warp_n * 32 + jp * 16 + b_row) * PITCH +
                                ks * 32 + b_coff;
                ldmatrix_x4(b, addr);
#pragma unroll
                for (int mi = 0; mi < 4; mi++) {
                    mma16816(acc[mi][jp * 2 + 0], a[mi], b[0], b[1]);
                    mma16816(acc[mi][jp * 2 + 1], a[mi], b[2], b[3]);
                }
            }
        }
        __syncthreads();
        if (c + 2 < nchunk) {
            const char* srcA = gA + (size_t)(c + 2) * 16384;
            const char* srcB = gB + (size_t)(c + 2) * 16384;
            uint32_t st = sb + (c & 1) * STAGE_SZ;
#pragma unroll
            for (int j = 0; j < 4; j++) {
                int i = tid + j * 256;
                int r = i >> 3, q = i & 7;
                cpasync16(st + r * PITCH + q * 16, srcA + r * 128 + q * 16);
            }
#pragma unroll
            for (int j = 0; j < 4; j++) {
                int i = tid + j * 256;
                int r = i >> 3, q = i & 7;
                cpasync16(st + STAGE_B + r * PITCH + q * 16, srcB + r * 128 + q * 16);
            }
        }
        asm volatile("cp.async.commit_group;" ::: "memory");
    }

    const int g = lane >> 2, tq = lane & 3;
#pragma unroll
    for (int mi = 0; mi < 4; mi++) {
        int row = warp_m * 64 + mi * 16 + g;
#pragma unroll
        for (int nj = 0; nj < 4; nj++) {
            int col = n0 + warp_n * 32 + nj * 8 + 2 * tq;
            float b0 = bias[col], b1 = bias[col + 1];
            float2 v0 = make_float2(acc[mi][nj][0] + b0, acc[mi][nj][1] + b1);
            float2 v1 = make_float2(acc[mi][nj][2] + b0, acc[mi][nj][3] + b1);
            if (MODE == 0) {
                *(float2*)(dst + (size_t)row * ldc + col) = v0;
                *(float2*)(dst + (size_t)(row + 8) * ldc + col) = v1;
            } else {
                float* bases[4] = {dst, d1, d2, d3};
                float* base = bases[col >> 8];
                int w = col & 255;
                *(float2*)(base + (size_t)row * 256 + w) = v0;
                *(float2*)(base + (size_t)(row + 8) * 256 + w) = v1;
            }
        }
    }
}

// In-place log_softmax over rows of length V (one block per row, 512 threads)
__global__ void logsoftmax_kernel(float* __restrict__ base) {
    float* x = base + (size_t)blockIdx.x * Vv;
    __shared__ float sred[16];
    __shared__ float sval;
    const int tid = threadIdx.x;
    const int wid = tid >> 5;

    float m = -3.4e38f;
    for (int i = tid; i < Vv; i += 512) m = fmaxf(m, x[i]);
#pragma unroll
    for (int o = 16; o; o >>= 1) m = fmaxf(m, __shfl_xor_sync(0xffffffffu, m, o));
    if ((tid & 31) == 0) sred[wid] = m;
    __syncthreads();
    if (tid < 32) {
        float v = (tid < 16) ? sred[tid] : -3.4e38f;
#pragma unroll
        for (int o = 8; o; o >>= 1) v = fmaxf(v, __shfl_xor_sync(0xffffffffu, v, o));
        if (tid == 0) sval = v;
    }
    __syncthreads();
    m = sval;

    float s = 0.0f;
    for (int i = tid; i < Vv; i += 512) s += expf(x[i] - m);
#pragma unroll
    for (int o = 16; o; o >>= 1) s += __shfl_xor_sync(0xffffffffu, s, o);
    __syncthreads();
    if ((tid & 31) == 0) sred[wid] = s;
    __syncthreads();
    if (tid < 32) {
        float v = (tid < 16) ? sred[tid] : 0.0f;
#pragma unroll
        for (int o = 8; o; o >>= 1) v += __shfl_xor_sync(0xffffffffu, v, o);
        if (tid == 0) sval = m + logf(v);
    }
    __syncthreads();
    float lz = sval;
    for (int i = tid; i < Vv; i += 512) x[i] -= lz;
}

extern "C" void kernel_launch(void* const* d_in, const int* in_sizes, int n_in,
                              void* d_out, int out_size) {
    const float* features = (const float*)d_in[0];
    const int* captions = (const int*)d_in[1];
    // d_in[2] lengths: unused (all == T)
    const float* noise   = (const float*)d_in[3];
    const float* embed_W = (const float*)d_in[4];
    const float* W_ih    = (const float*)d_in[5];
    const float* W_hh    = (const float*)d_in[6];
    const float* b_ih    = (const float*)d_in[7];
    const float* b_hh    = (const float*)d_in[8];
    const float* qz_W    = (const float*)d_in[9];
    const float* qz_b    = (const float*)d_in[10];
    const float* prior_W = (const float*)d_in[11];
    const float* prior_b = (const float*)d_in[12];
    const float* qx_W    = (const float*)d_in[13];
    const float* qx_b    = (const float*)d_in[14];
    float* out = (float*)d_out;

    __nv_bfloat16 *pAg, *pApq, *pAqx, *pBg, *pBpq, *pBqx;
    float *pbsum, *pbpq, *pgates;
    cudaGetSymbolAddress((void**)&pAg, gAg);
    cudaGetSymbolAddress((void**)&pApq, gApq);
    cudaGetSymbolAddress((void**)&pAqx, gAqx);
    cudaGetSymbolAddress((void**)&pBg, gBg);
    cudaGetSymbolAddress((void**)&pBpq, gBpq);
    cudaGetSymbolAddress((void**)&pBqx, gBqx);
    cudaGetSymbolAddress((void**)&pbsum, g_bsum);
    cudaGetSymbolAddress((void**)&pbpq, g_bias_pq);
    cudaGetSymbolAddress((void**)&pgates, g_gates);

    cudaFuncSetAttribute(tc_gemm<0>, cudaFuncAttributeMaxDynamicSharedMemorySize, 2 * STAGE_SZ);
    cudaFuncSetAttribute(tc_gemm<1>, cudaFuncAttributeMaxDynamicSharedMemorySize, 2 * STAGE_SZ);

    // one-time prep
    {
        int tot = Tt * Bb * Ee + 4 * Hh + 1024 + Bb * Hh;
        prep_misc_kernel<<<(tot + 255) / 256, 256>>>(b_ih, b_hh, qz_b, prior_b, embed_W, captions);
        size_t n;
        n = (size_t)2048 * 3840;
        prep_wg_kernel<<<(int)((n + 255) / 256), 256>>>(W_ih, W_hh);
        n = (size_t)1024 * 3072;
        prep_wpq_kernel<<<(int)((n + 255) / 256), 256>>>(qz_W, prior_W);
        n = (size_t)Vv * 2304;
        prep_wqx_kernel<<<(int)((n + 255) / 256), 256>>>(qx_W);
    }

    // initial LSTM step (fp32, one-time): gates = features @ W_ih[:, :512]^T + bsum
    {
        dim3 grid(Bb / 32, 2048 / 64);
        sgemm_bt<32, 64, 8, 4, 4><<<grid, 128>>>(features, Ee, W_ih, 768, pbsum,
                                                 pgates, 2048, Bb, 2048, Ee);
        lstm_kernel<<<(Bb * Hh + 255) / 256, 256>>>();
    }

    for (int t = 0; t < Tt; t++) {
        build1_kernel<<<(Bb * 1024 + 255) / 256, 256>>>(t);

        // prior+qz fused GEMM -> q_mu, q_sigma, p_mu, p_sigma
        tc_gemm<1><<<NT_PQ, 256, 2 * STAGE_SZ>>>(
            pApq, pBpq, NCH_PQ, pbpq,
            out + OFF_QMU + (size_t)t * Bb * Ll, 0,
            out + OFF_QSIG + (size_t)t * Bb * Ll,
            out + OFF_PMU + (size_t)t * Bb * Ll,
            out + OFF_PSIG + (size_t)t * Bb * Ll);

        build2_kernel<<<(Bb * Ll + 255) / 256, 256>>>(noise, out, t);

        // gates GEMM
        tc_gemm<0><<<NT_G, 256, 2 * STAGE_SZ>>>(
            pAg, pBg, NCH_G, pbsum, pgates, 2048, nullptr, nullptr, nullptr);

        // qx GEMM + log-softmax
        float* qx_dst = out + OFF_QX + (size_t)t * Bb * Vv;
        tc_gemm<0><<<NT_QX, 256, 2 * STAGE_SZ>>>(
            pAqx, pBqx, NCH_QX, qx_b, qx_dst, Vv, nullptr, nullptr, nullptr);
        logsoftmax_kernel<<<Bb, 512>>>(qx_dst);

        lstm_kernel<<<(Bb * Hh + 255) / 256, 256>>>();
    }
}

// round 5
// speedup vs baseline: 4.1144x; 2.0460x over previous
#include <cuda_runtime.h>
#include <cuda_bf16.h>
#include <math.h>
#include <stdint.h>

// Problem constants
#define Bb 128
#define Tt 32
#define Ee 512
#define Hh 512
#define Ll 256
#define Vv 16000

#define NCH_G  60      // gates: K2=3840
#define NCH_PQ 48      // pq: K2=3072
#define NCH_QX 36      // qx: K2=2304
#define NT_G   16
#define NT_PQ  8
#define NT_QX  125

// Output layout: p_mus, p_sigmas, q_mus, q_sigmas, q_xs
#define OFF_PMU  ((size_t)0)
#define OFF_PSIG ((size_t)Tt * Bb * Ll)
#define OFF_QMU  ((size_t)2 * Tt * Bb * Ll)
#define OFF_QSIG ((size_t)3 * Tt * Bb * Ll)
#define OFF_QX   ((size_t)4 * Tt * Bb * Ll)

// ---------------- device scratch ----------------
__device__ float g_emb[Tt * Bb * Ee];
__device__ float g_bsum[4 * Hh];
__device__ float g_bias_pq[1024];
__device__ float g_zb[2048];                  // zero bias
__device__ float g_h[Bb * Hh];
__device__ float g_c[Bb * Hh];
__device__ float g_pqp[3][Bb * 1024];         // pq split-K partials
__device__ float g_gp[3][Bb * 2048];          // gates split-K partials

// Weight images (once): [tile][chunk][row 128][64] bf16
__device__ __align__(16) __nv_bfloat16 gBg[(size_t)NT_G * NCH_G * 8192];
__device__ __align__(16) __nv_bfloat16 gBpq[(size_t)NT_PQ * NCH_PQ * 8192];
__device__ __align__(16) __nv_bfloat16 gBqx[(size_t)NT_QX * NCH_QX * 8192];
// A images (rebuilt per step): [chunk][row 128][64]
__device__ __align__(16) __nv_bfloat16 gAg[NCH_G * 8192];
__device__ __align__(16) __nv_bfloat16 gApq[NCH_PQ * 8192];
__device__ __align__(16) __nv_bfloat16 gAqx[NCH_QX * 8192];

__device__ __forceinline__ float sigf(float x) { return 1.0f / (1.0f + expf(-x)); }

__device__ __forceinline__ uint32_t s2u(const void* p) {
    uint32_t a;
    asm("{ .reg .u64 t; cvta.to.shared.u64 t, %1; cvt.u32.u64 %0, t; }" : "=r"(a) : "l"(p));
    return a;
}
__device__ __forceinline__ void cpasync16(uint32_t dst, const void* src) {
    asm volatile("cp.async.cg.shared.global [%0], [%1], 16;"
                 :: "r"(dst), "l"(__cvta_generic_to_global(src)) : "memory");
}
__device__ __forceinline__ void ldmatrix_x4(uint32_t* r, uint32_t addr) {
    asm volatile("ldmatrix.sync.aligned.m8n8.x4.shared.b16 {%0,%1,%2,%3}, [%4];"
                 : "=r"(r[0]), "=r"(r[1]), "=r"(r[2]), "=r"(r[3]) : "r"(addr));
}
__device__ __forceinline__ void mma16816(float* c, const uint32_t* a, uint32_t b0, uint32_t b1) {
    asm volatile(
        "mma.sync.aligned.m16n8k16.row.col.f32.bf16.bf16.f32 "
        "{%0,%1,%2,%3}, {%4,%5,%6,%7}, {%8,%9}, {%0,%1,%2,%3};"
        : "+f"(c[0]), "+f"(c[1]), "+f"(c[2]), "+f"(c[3])
        : "r"(a[0]), "r"(a[1]), "r"(a[2]), "r"(a[3]), "r"(b0), "r"(b1));
}
__device__ __forceinline__ size_t ipos(int k2, int m) {
    return (((size_t)(k2 >> 6) * 128 + m) << 6) + (k2 & 63);
}

// ---------------- one-time prep ----------------
__global__ void prep_misc_kernel(const float* __restrict__ b_ih, const float* __restrict__ b_hh,
                                 const float* __restrict__ qz_b, const float* __restrict__ prior_b,
                                 const float* __restrict__ embed_W, const int* __restrict__ captions) {
    int idx = blockIdx.x * blockDim.x + threadIdx.x;
    const int N_EMB = Tt * Bb * Ee;
    if (idx < N_EMB) {
        int tb = idx / Ee, e = idx % Ee;
        int t = tb / Bb, b = tb % Bb;
        g_emb[idx] = embed_W[(size_t)captions[b * Tt + t] * Ee + e];
    } else if (idx < N_EMB + 2048) {
        int n = idx - N_EMB;
        g_bsum[n] = b_ih[n] + b_hh[n];
    } else if (idx < N_EMB + 2048 + 1024) {
        int n = idx - N_EMB - 2048;
        g_bias_pq[n] = (n < 512) ? qz_b[n] : prior_b[n - 512];
    } else if (idx < N_EMB + 2048 + 1024 + 2048) {
        g_zb[idx - N_EMB - 2048 - 1024] = 0.0f;
    } else if (idx < N_EMB + 2048 + 1024 + 2048 + Bb * Hh) {
        g_c[idx - N_EMB - 2048 - 1024 - 2048] = 0.0f;
    } else if (idx < N_EMB + 2048 + 1024 + 2048 + Bb * Hh + 2 * Bb * 2048) {
        int j = idx - N_EMB - 2048 - 1024 - 2048 - Bb * Hh;
        if (j < Bb * 2048) g_gp[1][j] = 0.0f;
        else g_gp[2][j - Bb * 2048] = 0.0f;
    }
}

// gates weights: N=2048, K order [e(512), z(256), h(512)], fold B=[hi|lo|hi]
__global__ void prep_wg_kernel(const float* __restrict__ W_ih, const float* __restrict__ W_hh) {
    int idx = blockIdx.x * blockDim.x + threadIdx.x;
    if (idx >= 2048 * 1280) return;
    int n = idx / 1280, k = idx - n * 1280;
    float v = (k < 768) ? W_ih[(size_t)n * 768 + k] : W_hh[(size_t)n * 512 + (k - 768)];
    __nv_bfloat16 hi = __float2bfloat16(v);
    __nv_bfloat16 lo = __float2bfloat16(v - __bfloat162float(hi));
    int tile = n >> 7, row = n & 127;
    __nv_bfloat16* base = gBg + (size_t)tile * NCH_G * 8192;
    base[ipos(k, row)] = hi;
    base[ipos(k + 1280, row)] = lo;
    base[ipos(k + 2560, row)] = hi;
}

// pq weights: N=1024 (qz 0-511, prior 512-1023 padded over e), K order [e, h]
__global__ void prep_wpq_kernel(const float* __restrict__ qz_W, const float* __restrict__ prior_W) {
    int idx = blockIdx.x * blockDim.x + threadIdx.x;
    if (idx >= 1024 * 1024) return;
    int n = idx >> 10, k = idx & 1023;
    float v;
    if (n < 512) v = qz_W[(size_t)n * 1024 + k];
    else v = (k < 512) ? 0.0f : prior_W[(size_t)(n - 512) * 512 + (k - 512)];
    __nv_bfloat16 hi = __float2bfloat16(v);
    __nv_bfloat16 lo = __float2bfloat16(v - __bfloat162float(hi));
    int tile = n >> 7, row = n & 127;
    __nv_bfloat16* base = gBpq + (size_t)tile * NCH_PQ * 8192;
    base[ipos(k, row)] = hi;
    base[ipos(k + 1024, row)] = lo;
    base[ipos(k + 2048, row)] = hi;
}

// qx weights: N=16000, K order [z(256), h(512)]
__global__ void prep_wqx_kernel(const float* __restrict__ qx_W) {
    int idx = blockIdx.x * blockDim.x + threadIdx.x;
    if (idx >= Vv * 768) return;
    int n = idx / 768, k = idx - n * 768;
    float v = qx_W[(size_t)n * 768 + k];
    __nv_bfloat16 hi = __float2bfloat16(v);
    __nv_bfloat16 lo = __float2bfloat16(v - __bfloat162float(hi));
    int tile = n >> 7, row = n & 127;
    __nv_bfloat16* base = gBqx + (size_t)tile * NCH_QX * 8192;
    base[ipos(k, row)] = hi;
    base[ipos(k + 768, row)] = lo;
    base[ipos(k + 1536, row)] = hi;
}

// ---------------- fp32 SGEMM (initial step only) ----------------
template <int BM, int BN, int BK, int TM, int TN>
__global__ void sgemm_bt(const float* __restrict__ A, int lda,
                         const float* __restrict__ Bw, int ldb,
                         const float* __restrict__ bias,
                         float* __restrict__ C0, int ldc0, int M, int N, int K) {
    constexpr int THREADS = (BM / TM) * (BN / TN);
    __shared__ float As[BK][BM];
    __shared__ float Bs[BK][BN];
    const int tid = threadIdx.x;
    const int block_m = blockIdx.x * BM;
    const int block_n = blockIdx.y * BN;
    const int tn_ = tid % (BN / TN);
    const int tm_ = tid / (BN / TN);

    float acc[TM][TN];
#pragma unroll
    for (int i = 0; i < TM; i++)
#pragma unroll
        for (int j = 0; j < TN; j++) acc[i][j] = 0.0f;

    constexpr int A_F4 = BM * BK / 4;
    constexpr int B_F4 = BN * BK / 4;
    for (int k0 = 0; k0 < K; k0 += BK) {
#pragma unroll
        for (int i = tid; i < A_F4; i += THREADS) {
            int row = i / (BK / 4), kq = i % (BK / 4);
            float4 v = *(const float4*)(A + (size_t)(block_m + row) * lda + k0 + kq * 4);
            As[kq * 4 + 0][row] = v.x; As[kq * 4 + 1][row] = v.y;
            As[kq * 4 + 2][row] = v.z; As[kq * 4 + 3][row] = v.w;
        }
#pragma unroll
        for (int i = tid; i < B_F4; i += THREADS) {
            int row = i / (BK / 4), kq = i % (BK / 4);
            float4 v = *(const float4*)(Bw + (size_t)(block_n + row) * ldb + k0 + kq * 4);
            Bs[kq * 4 + 0][row] = v.x; Bs[kq * 4 + 1][row] = v.y;
            Bs[kq * 4 + 2][row] = v.z; Bs[kq * 4 + 3][row] = v.w;
        }
        __syncthreads();
#pragma unroll
        for (int kk = 0; kk < BK; kk++) {
            float ra[TM], rb[TN];
#pragma unroll
            for (int i = 0; i < TM; i++) ra[i] = As[kk][tm_ * TM + i];
#pragma unroll
            for (int j = 0; j < TN; j++) rb[j] = Bs[kk][tn_ * TN + j];
#pragma unroll
            for (int i = 0; i < TM; i++)
#pragma unroll
                for (int j = 0; j < TN; j++) acc[i][j] = fmaf(ra[i], rb[j], acc[i][j]);
        }
        __syncthreads();
    }
#pragma unroll
    for (int i = 0; i < TM; i++) {
        int m = block_m + tm_ * TM + i;
#pragma unroll
        for (int j = 0; j < TN; j++) {
            int n = block_n + tn_ * TN + j;
            C0[(size_t)m * ldc0 + n] = acc[i][j] + bias[n];
        }
    }
}

// ---------------- split-bf16 mma GEMM body ----------------
#define PITCH 144
#define STAGE_B 18432
#define STAGE_SZ 36864

__device__ __forceinline__ void gemm_body(
    const __nv_bfloat16* __restrict__ Aimg, const __nv_bfloat16* __restrict__ Bimg,
    int nchunk, const float* __restrict__ bias, float* __restrict__ dst, int ldc, int n0) {
    extern __shared__ __align__(16) char smem[];
    const uint32_t sb = s2u(smem);
    const int tid = threadIdx.x;
    const int wid = tid >> 5;
    const int lane = tid & 31;
    const int warp_m = wid >> 2;
    const int warp_n = wid & 3;

    const char* gA = (const char*)Aimg;
    const char* gB = (const char*)Bimg;

    float acc[4][4][4];
#pragma unroll
    for (int i = 0; i < 4; i++)
#pragma unroll
        for (int j = 0; j < 4; j++)
#pragma unroll
            for (int q = 0; q < 4; q++) acc[i][j][q] = 0.0f;

    const int a_row = lane & 15;
    const int a_coff = (lane >> 4) << 4;
    const int b_row = ((lane >> 4) << 3) | (lane & 7);
    const int b_coff = ((lane >> 3) & 1) << 4;

#pragma unroll
    for (int s = 0; s < 2; s++) {
        const char* srcA = gA + (size_t)s * 16384;
        const char* srcB = gB + (size_t)s * 16384;
        uint32_t st = sb + s * STAGE_SZ;
#pragma unroll
        for (int j = 0; j < 4; j++) {
            int i = tid + j * 256;
            int r = i >> 3, q = i & 7;
            cpasync16(st + r * PITCH + q * 16, srcA + r * 128 + q * 16);
        }
#pragma unroll
        for (int j = 0; j < 4; j++) {
            int i = tid + j * 256;
            int r = i >> 3, q = i & 7;
            cpasync16(st + STAGE_B + r * PITCH + q * 16, srcB + r * 128 + q * 16);
        }
        asm volatile("cp.async.commit_group;" ::: "memory");
    }

    for (int c = 0; c < nchunk; c++) {
        if (c < nchunk - 2)
            asm volatile("cp.async.wait_group 1;" ::: "memory");
        else
            asm volatile("cp.async.wait_group 0;" ::: "memory");
        __syncthreads();

        const uint32_t stg = sb + (c & 1) * STAGE_SZ;
        const uint32_t As = stg;
        const uint32_t Bs = stg + STAGE_B;
#pragma unroll
        for (int ks = 0; ks < 4; ks++) {
            uint32_t a[4][4];
#pragma unroll
            for (int mi = 0; mi < 4; mi++) {
                uint32_t addr = As + (uint32_t)(warp_m * 64 + mi * 16 + a_row) * PITCH +
                                ks * 32 + a_coff;
                ldmatrix_x4(a[mi], addr);
            }
#pragma unroll
            for (int jp = 0; jp < 2; jp++) {
                uint32_t b[4];
                uint32_t addr = Bs + (uint32_t)(warp_n * 32 + jp * 16 + b_row) * PITCH +
                                ks * 32 + b_coff;
                ldmatrix_x4(b, addr);
#pragma unroll
                for (int mi = 0; mi < 4; mi++) {
                    mma16816(acc[mi][jp * 2 + 0], a[mi], b[0], b[1]);
                    mma16816(acc[mi][jp * 2 + 1], a[mi], b[2], b[3]);
                }
            }
        }
        __syncthreads();
        if (c + 2 < nchunk) {
            const char* srcA = gA + (size_t)(c + 2) * 16384;
            const char* srcB = gB + (size_t)(c + 2) * 16384;
            uint32_t st = sb + (c & 1) * STAGE_SZ;
#pragma unroll
            for (int j = 0; j < 4; j++) {
                int i = tid + j * 256;
                int r = i >> 3, q = i & 7;
                cpasync16(st + r * PITCH + q * 16, srcA + r * 128 + q * 16);
            }
#pragma unroll
            for (int j = 0; j < 4; j++) {
                int i = tid + j * 256;
                int r = i >> 3, q = i & 7;
                cpasync16(st + STAGE_B + r * PITCH + q * 16, srcB + r * 128 + q * 16);
            }
        }
        asm volatile("cp.async.commit_group;" ::: "memory");
    }

    const int g = lane >> 2, tq = lane & 3;
#pragma unroll
    for (int mi = 0; mi < 4; mi++) {
        int row = warp_m * 64 + mi * 16 + g;
#pragma unroll
        for (int nj = 0; nj < 4; nj++) {
            int col = n0 + warp_n * 32 + nj * 8 + 2 * tq;
            float b0 = bias[col], b1 = bias[col + 1];
            float2 v0 = make_float2(acc[mi][nj][0] + b0, acc[mi][nj][1] + b1);
            float2 v1 = make_float2(acc[mi][nj][2] + b0, acc[mi][nj][3] + b1);
            *(float2*)(dst + (size_t)row * ldc + col) = v0;
            *(float2*)(dst + (size_t)(row + 8) * ldc + col) = v1;
        }
    }
}

// pq GEMM: 24 CTAs = 3 K-segments x 8 N-tiles -> partials
__global__ void __launch_bounds__(256) pq_kernel() {
    int seg = blockIdx.x >> 3, tile = blockIdx.x & 7;
    gemm_body(gApq + (size_t)seg * 16 * 8192,
              gBpq + ((size_t)tile * NCH_PQ + seg * 16) * 8192,
              16, g_zb, g_pqp[seg], 1024, tile << 7);
}

// merged qx + gates GEMM: 125 qx tiles + 48 gates (3 segs x 16 tiles)
__global__ void __launch_bounds__(256) qxgates_kernel(const float* __restrict__ qx_b,
                                                      float* __restrict__ qx_dst) {
    int bx = blockIdx.x;
    if (bx < NT_QX) {
        gemm_body(gAqx, gBqx + (size_t)bx * NCH_QX * 8192, NCH_QX, qx_b, qx_dst, Vv, bx << 7);
    } else {
        int gi = bx - NT_QX;
        int seg = gi >> 4, tile = gi & 15;
        gemm_body(gAg + (size_t)seg * 20 * 8192,
                  gBg + ((size_t)tile * NCH_G + seg * 20) * 8192,
                  20, g_zb, g_gp[seg], 2048, tile << 7);
    }
}

// build2: combine pq partials -> 4 outputs; z = noise*qsig + qmu -> z-images
__global__ void build2_kernel(const float* __restrict__ noise, float* __restrict__ out, int t) {
    int idx = blockIdx.x * blockDim.x + threadIdx.x;
    if (idx >= Bb * Ll) return;
    int m = idx >> 8, l = idx & 255;
    const int r = m * 1024;
    float qmu = g_pqp[0][r + l] + g_pqp[1][r + l] + g_pqp[2][r + l] + g_bias_pq[l];
    float qsig = g_pqp[0][r + 256 + l] + g_pqp[1][r + 256 + l] + g_pqp[2][r + 256 + l] + g_bias_pq[256 + l];
    float pmu = g_pqp[0][r + 512 + l] + g_pqp[1][r + 512 + l] + g_pqp[2][r + 512 + l] + g_bias_pq[512 + l];
    float psig = g_pqp[0][r + 768 + l] + g_pqp[1][r + 768 + l] + g_pqp[2][r + 768 + l] + g_bias_pq[768 + l];
    size_t o = ((size_t)t * Bb + m) * Ll + l;
    out[OFF_QMU + o] = qmu;
    out[OFF_QSIG + o] = qsig;
    out[OFF_PMU + o] = pmu;
    out[OFF_PSIG + o] = psig;
    float z = noise[((size_t)m * Tt + t) * Ll + l] * qsig + qmu;
    __nv_bfloat16 hi = __float2bfloat16(z);
    __nv_bfloat16 lo = __float2bfloat16(z - __bfloat162float(hi));
    int kg = 512 + l;
    gAg[ipos(kg, m)] = hi;
    gAg[ipos(kg + 1280, m)] = hi;
    gAg[ipos(kg + 2560, m)] = lo;
    gAqx[ipos(l, m)] = hi;
    gAqx[ipos(l + 768, m)] = hi;
    gAqx[ipos(l + 1536, m)] = lo;
}

// mega-epilogue: logsoftmax (vb<128) + lstm-reduce + h-images (128<=vb<256)
// + e-images for step t_next (256<=vb<384). 512 threads.
__global__ void epilogue_kernel(int blk_base, int t_next, float* __restrict__ qx_dst) {
    __shared__ float sred[16];
    __shared__ float sval;
    const int vb = blockIdx.x + blk_base;
    const int tid = threadIdx.x;

    if (vb < 128) {
        float* x = qx_dst + (size_t)vb * Vv;
        float m = -3.4e38f;
        for (int i = tid; i < Vv; i += 512) m = fmaxf(m, x[i]);
#pragma unroll
        for (int o = 16; o; o >>= 1) m = fmaxf(m, __shfl_xor_sync(0xffffffffu, m, o));
        if ((tid & 31) == 0) sred[tid >> 5] = m;
        __syncthreads();
        if (tid < 32) {
            float v = (tid < 16) ? sred[tid] : -3.4e38f;
#pragma unroll
            for (int o = 8; o; o >>= 1) v = fmaxf(v, __shfl_xor_sync(0xffffffffu, v, o));
            if (tid == 0) sval = v;
        }
        __syncthreads();
        m = sval;
        float s = 0.0f;
        for (int i = tid; i < Vv; i += 512) s += expf(x[i] - m);
#pragma unroll
        for (int o = 16; o; o >>= 1) s += __shfl_xor_sync(0xffffffffu, s, o);
        __syncthreads();
        if ((tid & 31) == 0) sred[tid >> 5] = s;
        __syncthreads();
        if (tid < 32) {
            float v = (tid < 16) ? sred[tid] : 0.0f;
#pragma unroll
            for (int o = 8; o; o >>= 1) v += __shfl_xor_sync(0xffffffffu, v, o);
            if (tid == 0) sval = m + logf(v);
        }
        __syncthreads();
        float lz = sval;
        for (int i = tid; i < Vv; i += 512) x[i] -= lz;
    } else if (vb < 256) {
        int idx = (vb - 128) * 512 + tid;
        int b = idx >> 9, n = idx & 511;
        const int r = b * 2048;
        float gi = g_gp[0][r + n] + g_gp[1][r + n] + g_gp[2][r + n] + g_bsum[n];
        float gf = g_gp[0][r + 512 + n] + g_gp[1][r + 512 + n] + g_gp[2][r + 512 + n] + g_bsum[512 + n];
        float gg = g_gp[0][r + 1024 + n] + g_gp[1][r + 1024 + n] + g_gp[2][r + 1024 + n] + g_bsum[1024 + n];
        float go = g_gp[0][r + 1536 + n] + g_gp[1][r + 1536 + n] + g_gp[2][r + 1536 + n] + g_bsum[1536 + n];
        float c = sigf(gf) * g_c[idx] + sigf(gi) * tanhf(gg);
        g_c[idx] = c;
        float h = sigf(go) * tanhf(c);
        g_h[idx] = h;
        __nv_bfloat16 hi = __float2bfloat16(h);
        __nv_bfloat16 lo = __float2bfloat16(h - __bfloat162float(hi));
        int k = 512 + n;                         // pq K order [e, h]
        gApq[ipos(k, b)] = hi;
        gApq[ipos(k + 1024, b)] = hi;
        gApq[ipos(k + 2048, b)] = lo;
        int kg = 768 + n;                        // gates [e, z, h]
        gAg[ipos(kg, b)] = hi;
        gAg[ipos(kg + 1280, b)] = hi;
        gAg[ipos(kg + 2560, b)] = lo;
        int kq = 256 + n;                        // qx [z, h]
        gAqx[ipos(kq, b)] = hi;
        gAqx[ipos(kq + 768, b)] = hi;
        gAqx[ipos(kq + 1536, b)] = lo;
    } else {
        if (t_next >= Tt) return;
        int idx = (vb - 256) * 512 + tid;
        int m = idx >> 9, e = idx & 511;
        float v = g_emb[((size_t)t_next * Bb + m) * Ee + e];
        __nv_bfloat16 hi = __float2bfloat16(v);
        __nv_bfloat16 lo = __float2bfloat16(v - __bfloat162float(hi));
        gApq[ipos(e, m)] = hi;
        gApq[ipos(e + 1024, m)] = hi;
        gApq[ipos(e + 2048, m)] = lo;
        gAg[ipos(e, m)] = hi;
        gAg[ipos(e + 1280, m)] = hi;
        gAg[ipos(e + 2560, m)] = lo;
    }
}

extern "C" void kernel_launch(void* const* d_in, const int* in_sizes, int n_in,
                              void* d_out, int out_size) {
    const float* features = (const float*)d_in[0];
    const int* captions = (const int*)d_in[1];
    const float* noise   = (const float*)d_in[3];
    const float* embed_W = (const float*)d_in[4];
    const float* W_ih    = (const float*)d_in[5];
    const float* W_hh    = (const float*)d_in[6];
    const float* b_ih    = (const float*)d_in[7];
    const float* b_hh    = (const float*)d_in[8];
    const float* qz_W    = (const float*)d_in[9];
    const float* qz_b    = (const float*)d_in[10];
    const float* prior_W = (const float*)d_in[11];
    const float* prior_b = (const float*)d_in[12];
    const float* qx_W    = (const float*)d_in[13];
    const float* qx_b    = (const float*)d_in[14];
    float* out = (float*)d_out;

    float *pzb, *pgp0;
    cudaGetSymbolAddress((void**)&pzb, g_zb);
    cudaGetSymbolAddress((void**)&pgp0, g_gp);

    cudaFuncSetAttribute(pq_kernel, cudaFuncAttributeMaxDynamicSharedMemorySize, 2 * STAGE_SZ);
    cudaFuncSetAttribute(qxgates_kernel, cudaFuncAttributeMaxDynamicSharedMemorySize, 2 * STAGE_SZ);

    // one-time prep
    {
        int tot = Tt * Bb * Ee + 2048 + 1024 + 2048 + Bb * Hh + 2 * Bb * 2048;
        prep_misc_kernel<<<(tot + 255) / 256, 256>>>(b_ih, b_hh, qz_b, prior_b, embed_W, captions);
        prep_wg_kernel<<<(2048 * 1280 + 255) / 256, 256>>>(W_ih, W_hh);
        prep_wpq_kernel<<<(1024 * 1024 + 255) / 256, 256>>>(qz_W, prior_W);
        prep_wqx_kernel<<<(Vv * 768 + 255) / 256, 256>>>(qx_W);
    }

    // initial LSTM step: gates = features @ W_ih[:, :512]^T (zero bias -> g_gp[0]);
    // then lstm-reduce (adds bsum) + build images for t=0
    {
        dim3 grid(Bb / 32, 2048 / 64);
        sgemm_bt<32, 64, 8, 4, 4><<<grid, 128>>>(features, Ee, W_ih, 768, pzb,
                                                 pgp0, 2048, Bb, 2048, Ee);
        epilogue_kernel<<<256, 512>>>(128, 0, out);  // lstm + h-image + e-image(0); no softmax
    }

    for (int t = 0; t < Tt; t++) {
        pq_kernel<<<24, 256, 2 * STAGE_SZ>>>();
        build2_kernel<<<(Bb * Ll + 255) / 256, 256>>>(noise, out, t);
        float* qx_dst = out + OFF_QX + (size_t)t * Bb * Vv;
        qxgates_kernel<<<NT_QX + 48, 256, 2 * STAGE_SZ>>>(qx_b, qx_dst);
        epilogue_kernel<<<384, 512>>>(0, t + 1, qx_dst);
    }
}

// round 6
// speedup vs baseline: 4.2721x; 1.0383x over previous
#include <cuda_runtime.h>
#include <cuda_bf16.h>
#include <math.h>
#include <stdint.h>

// Problem constants
#define Bb 128
#define Tt 32
#define Ee 512
#define Hh 512
#define Ll 256
#define Vv 16000

#define NCH_G  60      // gates: K2=3840
#define NCH_PQ 48      // pq: K2=3072
#define NCH_QX 36      // qx: K2=2304
#define NT_G   16
#define NT_PQ  8
#define NT_QX  125

// Output layout: p_mus, p_sigmas, q_mus, q_sigmas, q_xs
#define OFF_PMU  ((size_t)0)
#define OFF_PSIG ((size_t)Tt * Bb * Ll)
#define OFF_QMU  ((size_t)2 * Tt * Bb * Ll)
#define OFF_QSIG ((size_t)3 * Tt * Bb * Ll)
#define OFF_QX   ((size_t)4 * Tt * Bb * Ll)

// ---------------- device scratch ----------------
__device__ float g_emb[Tt * Bb * Ee];
__device__ float g_bsum[4 * Hh];
__device__ float g_bias_pq[1024];
__device__ float g_zb[2048];
__device__ float g_h[Bb * Hh];
__device__ float g_c[Bb * Hh];
__device__ float g_pqp[3][Bb * 1024];
__device__ float g_gp[3][Bb * 2048];

// Weight images (once): [tile][chunk][row 128][64] bf16
__device__ __align__(16) __nv_bfloat16 gBg[(size_t)NT_G * NCH_G * 8192];
__device__ __align__(16) __nv_bfloat16 gBpq[(size_t)NT_PQ * NCH_PQ * 8192];
__device__ __align__(16) __nv_bfloat16 gBqx[(size_t)NT_QX * NCH_QX * 8192];
// A images: pq/gates single (s0-only), qx double-buffered by step parity
__device__ __align__(16) __nv_bfloat16 gAg[NCH_G * 8192];
__device__ __align__(16) __nv_bfloat16 gApq[NCH_PQ * 8192];
__device__ __align__(16) __nv_bfloat16 gAqx2[2][NCH_QX * 8192];

__device__ __forceinline__ float sigf(float x) { return 1.0f / (1.0f + expf(-x)); }

__device__ __forceinline__ uint32_t s2u(const void* p) {
    uint32_t a;
    asm("{ .reg .u64 t; cvta.to.shared.u64 t, %1; cvt.u32.u64 %0, t; }" : "=r"(a) : "l"(p));
    return a;
}
__device__ __forceinline__ void cpasync16(uint32_t dst, const void* src) {
    asm volatile("cp.async.cg.shared.global [%0], [%1], 16;"
                 :: "r"(dst), "l"(__cvta_generic_to_global(src)) : "memory");
}
__device__ __forceinline__ void ldmatrix_x4(uint32_t* r, uint32_t addr) {
    asm volatile("ldmatrix.sync.aligned.m8n8.x4.shared.b16 {%0,%1,%2,%3}, [%4];"
                 : "=r"(r[0]), "=r"(r[1]), "=r"(r[2]), "=r"(r[3]) : "r"(addr));
}
__device__ __forceinline__ void mma16816(float* c, const uint32_t* a, uint32_t b0, uint32_t b1) {
    asm volatile(
        "mma.sync.aligned.m16n8k16.row.col.f32.bf16.bf16.f32 "
        "{%0,%1,%2,%3}, {%4,%5,%6,%7}, {%8,%9}, {%0,%1,%2,%3};"
        : "+f"(c[0]), "+f"(c[1]), "+f"(c[2]), "+f"(c[3])
        : "r"(a[0]), "r"(a[1]), "r"(a[2]), "r"(a[3]), "r"(b0), "r"(b1));
}
__device__ __forceinline__ size_t ipos(int k2, int m) {
    return (((size_t)(k2 >> 6) * 128 + m) << 6) + (k2 & 63);
}
// pack 4 bf16 into 8 bytes
__device__ __forceinline__ unsigned long long pk4(__nv_bfloat16 a, __nv_bfloat16 b,
                                                  __nv_bfloat16 c, __nv_bfloat16 d) {
    union { __nv_bfloat16 h[4]; unsigned long long u; } t;
    t.h[0] = a; t.h[1] = b; t.h[2] = c; t.h[3] = d;
    return t.u;
}
__device__ __forceinline__ void cvt4(float4 v, unsigned long long& hi, unsigned long long& lo) {
    __nv_bfloat16 h0 = __float2bfloat16(v.x), h1 = __float2bfloat16(v.y);
    __nv_bfloat16 h2 = __float2bfloat16(v.z), h3 = __float2bfloat16(v.w);
    hi = pk4(h0, h1, h2, h3);
    lo = pk4(__float2bfloat16(v.x - __bfloat162float(h0)),
             __float2bfloat16(v.y - __bfloat162float(h1)),
             __float2bfloat16(v.z - __bfloat162float(h2)),
             __float2bfloat16(v.w - __bfloat162float(h3)));
}
__device__ __forceinline__ void st8(__nv_bfloat16* p, unsigned long long v) {
    *(unsigned long long*)p = v;
}

// ---------------- one-time prep (vectorized) ----------------
#define N_EMB4 (Tt * Bb * Ee / 4)
__global__ void prep_misc_kernel(const float* __restrict__ b_ih, const float* __restrict__ b_hh,
                                 const float* __restrict__ qz_b, const float* __restrict__ prior_b,
                                 const float* __restrict__ embed_W, const int* __restrict__ captions) {
    int i4 = blockIdx.x * blockDim.x + threadIdx.x;
    if (i4 < N_EMB4) {
        int j = i4 * 4;
        int tb = j >> 9, e = j & 511;
        int t = tb / Bb, b = tb % Bb;
        *(float4*)(g_emb + j) = *(const float4*)(embed_W + (size_t)captions[b * Tt + t] * Ee + e);
        return;
    }
    i4 -= N_EMB4;
    if (i4 < 512) {
        int n = i4 * 4;
        float4 a = *(const float4*)(b_ih + n), b = *(const float4*)(b_hh + n);
        *(float4*)(g_bsum + n) = make_float4(a.x + b.x, a.y + b.y, a.z + b.z, a.w + b.w);
        return;
    }
    i4 -= 512;
    if (i4 < 256) {
        int n = i4 * 4;
        *(float4*)(g_bias_pq + n) = (n < 512) ? *(const float4*)(qz_b + n)
                                              : *(const float4*)(prior_b + n - 512);
        return;
    }
    i4 -= 256;
    if (i4 < 512) { *(float4*)(g_zb + i4 * 4) = make_float4(0, 0, 0, 0); return; }
    i4 -= 512;
    if (i4 < Bb * Hh / 4) { *(float4*)(g_c + i4 * 4) = make_float4(0, 0, 0, 0); return; }
    i4 -= Bb * Hh / 4;
    if (i4 < 2 * Bb * 2048 / 4) {
        int j = i4 * 4;
        if (j < Bb * 2048) *(float4*)(&g_gp[1][0] + j) = make_float4(0, 0, 0, 0);
        else *(float4*)(&g_gp[2][0] + j - Bb * 2048) = make_float4(0, 0, 0, 0);
    }
}
#define PREP_MISC_TOT (N_EMB4 + 512 + 256 + 512 + Bb * Hh / 4 + 2 * Bb * 2048 / 4)

// gates weights: N=2048, K order [e(512), z(256), h(512)], fold [hi|lo|hi]
__global__ void prep_wg_kernel(const float* __restrict__ W_ih, const float* __restrict__ W_hh) {
    int idx = blockIdx.x * blockDim.x + threadIdx.x;
    if (idx >= 2048 * 320) return;
    int n = idx / 320, k = (idx - n * 320) * 4;
    float4 v = (k < 768) ? *(const float4*)(W_ih + (size_t)n * 768 + k)
                         : *(const float4*)(W_hh + (size_t)n * 512 + (k - 768));
    unsigned long long hi, lo;
    cvt4(v, hi, lo);
    int tile = n >> 7, row = n & 127;
    __nv_bfloat16* base = gBg + (size_t)tile * NCH_G * 8192;
    st8(base + ipos(k, row), hi);
    st8(base + ipos(k + 1280, row), lo);
    st8(base + ipos(k + 2560, row), hi);
}

// pq weights: N=1024 (qz 0-511, prior 512-1023 padded over e), K order [e, h]
__global__ void prep_wpq_kernel(const float* __restrict__ qz_W, const float* __restrict__ prior_W) {
    int idx = blockIdx.x * blockDim.x + threadIdx.x;
    if (idx >= 1024 * 256) return;
    int n = idx >> 8, k = (idx & 255) << 2;
    float4 v;
    if (n < 512) v = *(const float4*)(qz_W + (size_t)n * 1024 + k);
    else if (k < 512) v = make_float4(0, 0, 0, 0);
    else v = *(const float4*)(prior_W + (size_t)(n - 512) * 512 + (k - 512));
    unsigned long long hi, lo;
    cvt4(v, hi, lo);
    int tile = n >> 7, row = n & 127;
    __nv_bfloat16* base = gBpq + (size_t)tile * NCH_PQ * 8192;
    st8(base + ipos(k, row), hi);
    st8(base + ipos(k + 1024, row), lo);
    st8(base + ipos(k + 2048, row), hi);
}

// qx weights: N=16000, K order [z(256), h(512)]
__global__ void prep_wqx_kernel(const float* __restrict__ qx_W) {
    int idx = blockIdx.x * blockDim.x + threadIdx.x;
    if (idx >= Vv * 192) return;
    int n = idx / 192, k = (idx - n * 192) * 4;
    float4 v = *(const float4*)(qx_W + (size_t)n * 768 + k);
    unsigned long long hi, lo;
    cvt4(v, hi, lo);
    int tile = n >> 7, row = n & 127;
    __nv_bfloat16* base = gBqx + (size_t)tile * NCH_QX * 8192;
    st8(base + ipos(k, row), hi);
    st8(base + ipos(k + 768, row), lo);
    st8(base + ipos(k + 1536, row), hi);
}

// ---------------- fp32 SGEMM (initial step only) ----------------
template <int BM, int BN, int BK, int TM, int TN>
__global__ void sgemm_bt(const float* __restrict__ A, int lda,
                         const float* __restrict__ Bw, int ldb,
                         const float* __restrict__ bias,
                         float* __restrict__ C0, int ldc0, int M, int N, int K) {
    constexpr int THREADS = (BM / TM) * (BN / TN);
    __shared__ float As[BK][BM];
    __shared__ float Bs[BK][BN];
    const int tid = threadIdx.x;
    const int block_m = blockIdx.x * BM;
    const int block_n = blockIdx.y * BN;
    const int tn_ = tid % (BN / TN);
    const int tm_ = tid / (BN / TN);

    float acc[TM][TN];
#pragma unroll
    for (int i = 0; i < TM; i++)
#pragma unroll
        for (int j = 0; j < TN; j++) acc[i][j] = 0.0f;

    constexpr int A_F4 = BM * BK / 4;
    constexpr int B_F4 = BN * BK / 4;
    for (int k0 = 0; k0 < K; k0 += BK) {
#pragma unroll
        for (int i = tid; i < A_F4; i += THREADS) {
            int row = i / (BK / 4), kq = i % (BK / 4);
            float4 v = *(const float4*)(A + (size_t)(block_m + row) * lda + k0 + kq * 4);
            As[kq * 4 + 0][row] = v.x; As[kq * 4 + 1][row] = v.y;
            As[kq * 4 + 2][row] = v.z; As[kq * 4 + 3][row] = v.w;
        }
#pragma unroll
        for (int i = tid; i < B_F4; i += THREADS) {
            int row = i / (BK / 4), kq = i % (BK / 4);
            float4 v = *(const float4*)(Bw + (size_t)(block_n + row) * ldb + k0 + kq * 4);
            Bs[kq * 4 + 0][row] = v.x; Bs[kq * 4 + 1][row] = v.y;
            Bs[kq * 4 + 2][row] = v.z; Bs[kq * 4 + 3][row] = v.w;
        }
        __syncthreads();
#pragma unroll
        for (int kk = 0; kk < BK; kk++) {
            float ra[TM], rb[TN];
#pragma unroll
            for (int i = 0; i < TM; i++) ra[i] = As[kk][tm_ * TM + i];
#pragma unroll
            for (int j = 0; j < TN; j++) rb[j] = Bs[kk][tn_ * TN + j];
#pragma unroll
            for (int i = 0; i < TM; i++)
#pragma unroll
                for (int j = 0; j < TN; j++) acc[i][j] = fmaf(ra[i], rb[j], acc[i][j]);
        }
        __syncthreads();
    }
#pragma unroll
    for (int i = 0; i < TM; i++) {
        int m = block_m + tm_ * TM + i;
#pragma unroll
        for (int j = 0; j < TN; j++) {
            int n = block_n + tn_ * TN + j;
            C0[(size_t)m * ldc0 + n] = acc[i][j] + bias[n];
        }
    }
}

// ---------------- split-bf16 mma GEMM body (3-stage pipeline) ----------------
#define PITCH 144
#define STAGE_B 18432
#define STAGE_SZ 36864
#define SM3 (3 * STAGE_SZ)

__device__ __forceinline__ void load_stage(uint32_t st, const char* srcA, const char* srcB, int tid) {
#pragma unroll
    for (int j = 0; j < 4; j++) {
        int i = tid + j * 256;
        int r = i >> 3, q = i & 7;
        cpasync16(st + r * PITCH + q * 16, srcA + r * 128 + q * 16);
    }
#pragma unroll
    for (int j = 0; j < 4; j++) {
        int i = tid + j * 256;
        int r = i >> 3, q = i & 7;
        cpasync16(st + STAGE_B + r * PITCH + q * 16, srcB + r * 128 + q * 16);
    }
    asm volatile("cp.async.commit_group;" ::: "memory");
}

__device__ __forceinline__ void gemm_body(
    const __nv_bfloat16* __restrict__ Aimg, const __nv_bfloat16* __restrict__ Bimg,
    int nchunk, const float* __restrict__ bias, float* __restrict__ dst, int ldc, int n0) {
    extern __shared__ __align__(16) char smem[];
    const uint32_t sb = s2u(smem);
    const int tid = threadIdx.x;
    const int wid = tid >> 5;
    const int lane = tid & 31;
    const int warp_m = wid >> 2;
    const int warp_n = wid & 3;

    const char* gA = (const char*)Aimg;
    const char* gB = (const char*)Bimg;

    float acc[4][4][4];
#pragma unroll
    for (int i = 0; i < 4; i++)
#pragma unroll
        for (int j = 0; j < 4; j++)
#pragma unroll
            for (int q = 0; q < 4; q++) acc[i][j][q] = 0.0f;

    const int a_row = lane & 15;
    const int a_coff = (lane >> 4) << 4;
    const int b_row = ((lane >> 4) << 3) | (lane & 7);
    const int b_coff = ((lane >> 3) & 1) << 4;

#pragma unroll
    for (int s = 0; s < 3; s++)
        load_stage(sb + s * STAGE_SZ, gA + (size_t)s * 16384, gB + (size_t)s * 16384, tid);

    int slot = 0;
    for (int c = 0; c < nchunk; c++) {
        asm volatile("cp.async.wait_group 2;" ::: "memory");
        __syncthreads();

        const uint32_t stg = sb + slot * STAGE_SZ;
        const uint32_t As = stg;
        const uint32_t Bs = stg + STAGE_B;
#pragma unroll
        for (int ks = 0; ks < 4; ks++) {
            uint32_t a[4][4];
#pragma unroll
            for (int mi = 0; mi < 4; mi++) {
                uint32_t addr = As + (uint32_t)(warp_m * 64 + mi * 16 + a_row) * PITCH +
                                ks * 32 + a_coff;
                ldmatrix_x4(a[mi], addr);
            }
#pragma unroll
            for (int jp = 0; jp < 2; jp++) {
                uint32_t b[4];
                uint32_t addr = Bs + (uint32_t)(warp_n * 32 + jp * 16 + b_row) * PITCH +
                                ks * 32 + b_coff;
                ldmatrix_x4(b, addr);
#pragma unroll
                for (int mi = 0; mi < 4; mi++) {
                    mma16816(acc[mi][jp * 2 + 0], a[mi], b[0], b[1]);
                    mma16816(acc[mi][jp * 2 + 1], a[mi], b[2], b[3]);
                }
            }
        }
        __syncthreads();
        if (c + 3 < nchunk)
            load_stage(sb + slot * STAGE_SZ, gA + (size_t)(c + 3) * 16384,
                       gB + (size_t)(c + 3) * 16384, tid);
        else
            asm volatile("cp.async.commit_group;" ::: "memory");
        slot = (slot == 2) ? 0 : slot + 1;
    }

    const int g = lane >> 2, tq = lane & 3;
#pragma unroll
    for (int mi = 0; mi < 4; mi++) {
        int row = warp_m * 64 + mi * 16 + g;
#pragma unroll
        for (int nj = 0; nj < 4; nj++) {
            int col = n0 + warp_n * 32 + nj * 8 + 2 * tq;
            float b0 = bias[col], b1 = bias[col + 1];
            float2 v0 = make_float2(acc[mi][nj][0] + b0, acc[mi][nj][1] + b1);
            float2 v1 = make_float2(acc[mi][nj][2] + b0, acc[mi][nj][3] + b1);
            *(float2*)(dst + (size_t)row * ldc + col) = v0;
            *(float2*)(dst + (size_t)(row + 8) * ldc + col) = v1;
        }
    }
}

// pq: 24 CTAs = 3 K-segs x 8 N-tiles -> partials
__global__ void __launch_bounds__(256) pq_kernel() {
    int seg = blockIdx.x >> 3, tile = blockIdx.x & 7;
    gemm_body(gApq + (size_t)seg * 16 * 8192,
              gBpq + ((size_t)tile * NCH_PQ + seg * 16) * 8192,
              16, g_zb, g_pqp[seg], 1024, tile << 7);
}

// gates: 48 CTAs = 3 K-segs x 16 N-tiles -> partials
__global__ void __launch_bounds__(256) gates_kernel() {
    int seg = blockIdx.x >> 4, tile = blockIdx.x & 15;
    gemm_body(gAg + (size_t)seg * 20 * 8192,
              gBg + ((size_t)tile * NCH_G + seg * 20) * 8192,
              20, g_zb, g_gp[seg], 2048, tile << 7);
}

// qx: 125 CTAs, parity-selected A image
__global__ void __launch_bounds__(256) qx_kernel(const float* __restrict__ qx_b,
                                                 float* __restrict__ dst, int par) {
    gemm_body(gAqx2[par], gBqx + (size_t)blockIdx.x * NCH_QX * 8192,
              NCH_QX, qx_b, dst, Vv, blockIdx.x << 7);
}

// build2: reduce pq partials -> 4 outputs; z = noise*qsig+qmu -> z-images (vec4)
__global__ void build2_kernel(const float* __restrict__ noise, float* __restrict__ out,
                              int t, int par) {
    int i4 = blockIdx.x * 256 + threadIdx.x;
    if (i4 >= Bb * Ll / 4) return;
    int m = i4 >> 6;
    int l = (i4 & 63) << 2;
    const int r = m * 1024;
#define SUM4(off) ({ \
    float4 a = *(const float4*)(&g_pqp[0][0] + r + (off)); \
    float4 b = *(const float4*)(&g_pqp[1][0] + r + (off)); \
    float4 c = *(const float4*)(&g_pqp[2][0] + r + (off)); \
    float4 d = *(const float4*)(g_bias_pq + (off)); \
    make_float4(a.x + b.x + c.x + d.x, a.y + b.y + c.y + d.y, \
                a.z + b.z + c.z + d.z, a.w + b.w + c.w + d.w); })
    float4 qmu = SUM4(l);
    float4 qsig = SUM4(256 + l);
    float4 pmu = SUM4(512 + l);
    float4 psig = SUM4(768 + l);
#undef SUM4
    size_t o = ((size_t)t * Bb + m) * Ll + l;
    *(float4*)(out + OFF_QMU + o) = qmu;
    *(float4*)(out + OFF_QSIG + o) = qsig;
    *(float4*)(out + OFF_PMU + o) = pmu;
    *(float4*)(out + OFF_PSIG + o) = psig;
    float4 nz = *(const float4*)(noise + ((size_t)m * Tt + t) * Ll + l);
    float4 z = make_float4(nz.x * qsig.x + qmu.x, nz.y * qsig.y + qmu.y,
                           nz.z * qsig.z + qmu.z, nz.w * qsig.w + qmu.w);
    unsigned long long hi, lo;
    cvt4(z, hi, lo);
    int kg = 512 + l;
    st8(gAg + ipos(kg, m), hi);
    st8(gAg + ipos(kg + 1280, m), hi);
    st8(gAg + ipos(kg + 2560, m), lo);
    __nv_bfloat16* aqx = gAqx2[par];
    st8(aqx + ipos(l, m), hi);
    st8(aqx + ipos(l + 768, m), hi);
    st8(aqx + ipos(l + 1536, m), lo);
}

// epilogue: lstm-reduce + h-images (vb<32) + e-images for t_next (32<=vb<64); vec4
__global__ void epilogue_kernel(int t_next) {
    int vb = blockIdx.x, tid = threadIdx.x;
    int par = t_next & 1;
    if (vb < 32) {
        int i4 = vb * 512 + tid;                 // over Bb*Hh/4 = 16384
        int b = i4 >> 7;
        int n = (i4 & 127) << 2;
        const int r = b * 2048;
#define GSUM(off) ({ \
        float4 a = *(const float4*)(&g_gp[0][0] + r + (off)); \
        float4 x = *(const float4*)(&g_gp[1][0] + r + (off)); \
        float4 c = *(const float4*)(&g_gp[2][0] + r + (off)); \
        float4 d = *(const float4*)(g_bsum + (off)); \
        make_float4(a.x + x.x + c.x + d.x, a.y + x.y + c.y + d.y, \
                    a.z + x.z + c.z + d.z, a.w + x.w + c.w + d.w); })
        float4 gi = GSUM(n);
        float4 gf = GSUM(512 + n);
        float4 gg = GSUM(1024 + n);
        float4 go = GSUM(1536 + n);
#undef GSUM
        float4 co = *(const float4*)(g_c + b * 512 + n);
        float4 cn, h;
        cn.x = sigf(gf.x) * co.x + sigf(gi.x) * tanhf(gg.x);
        cn.y = sigf(gf.y) * co.y + sigf(gi.y) * tanhf(gg.y);
        cn.z = sigf(gf.z) * co.z + sigf(gi.z) * tanhf(gg.z);
        cn.w = sigf(gf.w) * co.w + sigf(gi.w) * tanhf(gg.w);
        h.x = sigf(go.x) * tanhf(cn.x);
        h.y = sigf(go.y) * tanhf(cn.y);
        h.z = sigf(go.z) * tanhf(cn.z);
        h.w = sigf(go.w) * tanhf(cn.w);
        *(float4*)(g_c + b * 512 + n) = cn;
        *(float4*)(g_h + b * 512 + n) = h;
        unsigned long long hi, lo;
        cvt4(h, hi, lo);
        int k = 512 + n;
        st8(gApq + ipos(k, b), hi);
        st8(gApq + ipos(k + 1024, b), hi);
        st8(gApq + ipos(k + 2048, b), lo);
        int kg = 768 + n;
        st8(gAg + ipos(kg, b), hi);
        st8(gAg + ipos(kg + 1280, b), hi);
        st8(gAg + ipos(kg + 2560, b), lo);
        __nv_bfloat16* aqx = gAqx2[par];
        int kq = 256 + n;
        st8(aqx + ipos(kq, b), hi);
        st8(aqx + ipos(kq + 768, b), hi);
        st8(aqx + ipos(kq + 1536, b), lo);
    } else {
        if (t_next >= Tt) return;
        int i4 = (vb - 32) * 512 + tid;          // over Bb*Ee/4 = 16384
        int m = i4 >> 7;
        int e = (i4 & 127) << 2;
        float4 v = *(const float4*)(g_emb + (((size_t)t_next * Bb + m) << 9) + e);
        unsigned long long hi, lo;
        cvt4(v, hi, lo);
        st8(gApq + ipos(e, m), hi);
        st8(gApq + ipos(e + 1024, m), hi);
        st8(gApq + ipos(e + 2048, m), lo);
        st8(gAg + ipos(e, m), hi);
        st8(gAg + ipos(e + 1280, m), hi);
        st8(gAg + ipos(e + 2560, m), lo);
    }
}

// In-place log_softmax over rows of length V (one block per row)
__global__ void softmax_kernel(float* __restrict__ base) {
    float* x = base + (size_t)blockIdx.x * Vv;
    __shared__ float sred[16];
    __shared__ float sval;
    const int tid = threadIdx.x;
    float m = -3.4e38f;
    for (int i = tid; i < Vv; i += 512) m = fmaxf(m, x[i]);
#pragma unroll
    for (int o = 16; o; o >>= 1) m = fmaxf(m, __shfl_xor_sync(0xffffffffu, m, o));
    if ((tid & 31) == 0) sred[tid >> 5] = m;
    __syncthreads();
    if (tid < 32) {
        float v = (tid < 16) ? sred[tid] : -3.4e38f;
#pragma unroll
        for (int o = 8; o; o >>= 1) v = fmaxf(v, __shfl_xor_sync(0xffffffffu, v, o));
        if (tid == 0) sval = v;
    }
    __syncthreads();
    m = sval;
    float s = 0.0f;
    for (int i = tid; i < Vv; i += 512) s += expf(x[i] - m);
#pragma unroll
    for (int o = 16; o; o >>= 1) s += __shfl_xor_sync(0xffffffffu, s, o);
    __syncthreads();
    if ((tid & 31) == 0) sred[tid >> 5] = s;
    __syncthreads();
    if (tid < 32) {
        float v = (tid < 16) ? sred[tid] : 0.0f;
#pragma unroll
        for (int o = 8; o; o >>= 1) v += __shfl_xor_sync(0xffffffffu, v, o);
        if (tid == 0) sval = m + logf(v);
    }
    __syncthreads();
    float lz = sval;
    for (int i = tid; i < Vv; i += 512) x[i] -= lz;
}

extern "C" void kernel_launch(void* const* d_in, const int* in_sizes, int n_in,
                              void* d_out, int out_size) {
    const float* features = (const float*)d_in[0];
    const int* captions = (const int*)d_in[1];
    const float* noise   = (const float*)d_in[3];
    const float* embed_W = (const float*)d_in[4];
    const float* W_ih    = (const float*)d_in[5];
    const float* W_hh    = (const float*)d_in[6];
    const float* b_ih    = (const float*)d_in[7];
    const float* b_hh    = (const float*)d_in[8];
    const float* qz_b    = (const float*)d_in[10];
    const float* qz_W    = (const float*)d_in[9];
    const float* prior_W = (const float*)d_in[11];
    const float* prior_b = (const float*)d_in[12];
    const float* qx_W    = (const float*)d_in[13];
    const float* qx_b    = (const float*)d_in[14];
    float* out = (float*)d_out;

    static cudaStream_t s1 = nullptr, s2 = nullptr;
    static cudaEvent_t evZ = nullptr, evQ0 = nullptr, evQ1 = nullptr, evJ1 = nullptr, evJ2 = nullptr;
    if (s1 == nullptr) {
        cudaStreamCreateWithFlags(&s1, cudaStreamNonBlocking);
        cudaStreamCreateWithFlags(&s2, cudaStreamNonBlocking);
        cudaEventCreateWithFlags(&evZ, cudaEventDisableTiming);
        cudaEventCreateWithFlags(&evQ0, cudaEventDisableTiming);
        cudaEventCreateWithFlags(&evQ1, cudaEventDisableTiming);
        cudaEventCreateWithFlags(&evJ1, cudaEventDisableTiming);
        cudaEventCreateWithFlags(&evJ2, cudaEventDisableTiming);
    }

    float *pzb, *pgp0;
    cudaGetSymbolAddress((void**)&pzb, g_zb);
    cudaGetSymbolAddress((void**)&pgp0, g_gp);

    cudaFuncSetAttribute(pq_kernel, cudaFuncAttributeMaxDynamicSharedMemorySize, SM3);
    cudaFuncSetAttribute(gates_kernel, cudaFuncAttributeMaxDynamicSharedMemorySize, SM3);
    cudaFuncSetAttribute(qx_kernel, cudaFuncAttributeMaxDynamicSharedMemorySize, SM3);

    // one-time prep
    prep_misc_kernel<<<(PREP_MISC_TOT + 255) / 256, 256>>>(b_ih, b_hh, qz_b, prior_b,
                                                           embed_W, captions);
    prep_wg_kernel<<<(2048 * 320 + 255) / 256, 256>>>(W_ih, W_hh);
    prep_wpq_kernel<<<(1024 * 256 + 255) / 256, 256>>>(qz_W, prior_W);
    prep_wqx_kernel<<<(Vv * 192 + 255) / 256, 256>>>(qx_W);

    // initial LSTM step: gates -> g_gp[0] (zero bias); epilogue reduces + images(t=0)
    {
        dim3 grid(Bb / 32, 2048 / 64);
        sgemm_bt<32, 64, 8, 4, 4><<<grid, 128>>>(features, Ee, W_ih, 768, pzb,
                                                 pgp0, 2048, Bb, 2048, Ee);
        epilogue_kernel<<<64, 512>>>(0);
    }

    for (int t = 0; t < Tt; t++) {
        pq_kernel<<<24, 256, SM3>>>();
        build2_kernel<<<32, 256>>>(noise, out, t, t & 1);
        cudaEventRecord(evZ, 0);
        cudaStreamWaitEvent(s1, evZ, 0);
        float* qx_dst = out + OFF_QX + (size_t)t * Bb * Vv;
        qx_kernel<<<NT_QX, 256, SM3, s1>>>(qx_b, qx_dst, t & 1);
        cudaEvent_t eq = (t & 1) ? evQ1 : evQ0;
        cudaEventRecord(eq, s1);
        cudaStreamWaitEvent(s2, eq, 0);
        softmax_kernel<<<128, 512, 0, s2>>>(qx_dst);
        gates_kernel<<<48, 256, SM3>>>();
        if (t >= 1) cudaStreamWaitEvent(0, (t & 1) ? evQ0 : evQ1, 0);  // qx(t-1) done
        epilogue_kernel<<<64, 512>>>(t + 1);
    }

    // join side streams back to the main stream
    cudaEventRecord(evJ1, s1);
    cudaStreamWaitEvent(0, evJ1, 0);
    cudaEventRecord(evJ2, s2);
    cudaStreamWaitEvent(0, evJ2, 0);
}

// round 7
// speedup vs baseline: 5.7081x; 1.3361x over previous
#include <cuda_runtime.h>
#include <cuda_bf16.h>
#include <math.h>
#include <stdint.h>

// Problem constants
#define Bb 128
#define Tt 32
#define Ee 512
#define Hh 512
#define Ll 256
#define Vv 16000

#define NCH_G  60      // gates: K2=3840
#define NCH_PQ 48      // pq: K2=3072
#define NCH_QX 36      // qx: K2=2304
#define NT_G   16
#define NT_PQ  8
#define NT_QX  84      // qx tiles of 192 cols: 84*192 = 16128 >= 16000
#define QROWS  192

// Output layout: p_mus, p_sigmas, q_mus, q_sigmas, q_xs
#define OFF_PMU  ((size_t)0)
#define OFF_PSIG ((size_t)Tt * Bb * Ll)
#define OFF_QMU  ((size_t)2 * Tt * Bb * Ll)
#define OFF_QSIG ((size_t)3 * Tt * Bb * Ll)
#define OFF_QX   ((size_t)4 * Tt * Bb * Ll)

// ---------------- device scratch ----------------
__device__ float g_emb[Tt * Bb * Ee];
__device__ float g_bsum[4 * Hh];
__device__ float g_bias_pq[1024];
__device__ float g_zb[2048];
__device__ float g_h[Bb * Hh];
__device__ float g_c[Bb * Hh];
__device__ float g_pqp[6][Bb * 1024];         // pq split-K partials (6 segs)
__device__ float g_gp[3][Bb * 2048];          // gates split-K partials (3 segs)

// Weight images (once)
__device__ __align__(16) __nv_bfloat16 gBg[(size_t)NT_G * NCH_G * 8192];
__device__ __align__(16) __nv_bfloat16 gBpq[(size_t)NT_PQ * NCH_PQ * 8192];
__device__ __align__(16) __nv_bfloat16 gBqx[(size_t)NT_QX * NCH_QX * QROWS * 64];
// A images: pq/gates single (s0-only), qx double-buffered by step parity
__device__ __align__(16) __nv_bfloat16 gAg[NCH_G * 8192];
__device__ __align__(16) __nv_bfloat16 gApq[NCH_PQ * 8192];
__device__ __align__(16) __nv_bfloat16 gAqx2[2][NCH_QX * 8192];

__device__ __forceinline__ float sigf(float x) { return 1.0f / (1.0f + expf(-x)); }

__device__ __forceinline__ uint32_t s2u(const void* p) {
    uint32_t a;
    asm("{ .reg .u64 t; cvta.to.shared.u64 t, %1; cvt.u32.u64 %0, t; }" : "=r"(a) : "l"(p));
    return a;
}
__device__ __forceinline__ void cpasync16(uint32_t dst, const void* src) {
    asm volatile("cp.async.cg.shared.global [%0], [%1], 16;"
                 :: "r"(dst), "l"(__cvta_generic_to_global(src)) : "memory");
}
__device__ __forceinline__ void ldmatrix_x4(uint32_t* r, uint32_t addr) {
    asm volatile("ldmatrix.sync.aligned.m8n8.x4.shared.b16 {%0,%1,%2,%3}, [%4];"
                 : "=r"(r[0]), "=r"(r[1]), "=r"(r[2]), "=r"(r[3]) : "r"(addr));
}
__device__ __forceinline__ void mma16816(float* c, const uint32_t* a, uint32_t b0, uint32_t b1) {
    asm volatile(
        "mma.sync.aligned.m16n8k16.row.col.f32.bf16.bf16.f32 "
        "{%0,%1,%2,%3}, {%4,%5,%6,%7}, {%8,%9}, {%0,%1,%2,%3};"
        : "+f"(c[0]), "+f"(c[1]), "+f"(c[2]), "+f"(c[3])
        : "r"(a[0]), "r"(a[1]), "r"(a[2]), "r"(a[3]), "r"(b0), "r"(b1));
}
__device__ __forceinline__ size_t ipos(int k2, int m) {       // 128-row images
    return (((size_t)(k2 >> 6) * 128 + m) << 6) + (k2 & 63);
}
__device__ __forceinline__ size_t ipos192(int k2, int m) {    // 192-row images
    return (((size_t)(k2 >> 6) * QROWS + m) << 6) + (k2 & 63);
}
__device__ __forceinline__ unsigned long long pk4(__nv_bfloat16 a, __nv_bfloat16 b,
                                                  __nv_bfloat16 c, __nv_bfloat16 d) {
    union { __nv_bfloat16 h[4]; unsigned long long u; } t;
    t.h[0] = a; t.h[1] = b; t.h[2] = c; t.h[3] = d;
    return t.u;
}
__device__ __forceinline__ void cvt4(float4 v, unsigned long long& hi, unsigned long long& lo) {
    __nv_bfloat16 h0 = __float2bfloat16(v.x), h1 = __float2bfloat16(v.y);
    __nv_bfloat16 h2 = __float2bfloat16(v.z), h3 = __float2bfloat16(v.w);
    hi = pk4(h0, h1, h2, h3);
    lo = pk4(__float2bfloat16(v.x - __bfloat162float(h0)),
             __float2bfloat16(v.y - __bfloat162float(h1)),
             __float2bfloat16(v.z - __bfloat162float(h2)),
             __float2bfloat16(v.w - __bfloat162float(h3)));
}
__device__ __forceinline__ void st8(__nv_bfloat16* p, unsigned long long v) {
    *(unsigned long long*)p = v;
}

// ---------------- one-time prep (vectorized) ----------------
#define N_EMB4 (Tt * Bb * Ee / 4)
__global__ void prep_misc_kernel(const float* __restrict__ b_ih, const float* __restrict__ b_hh,
                                 const float* __restrict__ qz_b, const float* __restrict__ prior_b,
                                 const float* __restrict__ embed_W, const int* __restrict__ captions) {
    int i4 = blockIdx.x * blockDim.x + threadIdx.x;
    if (i4 < N_EMB4) {
        int j = i4 * 4;
        int tb = j >> 9, e = j & 511;
        int t = tb / Bb, b = tb % Bb;
        *(float4*)(g_emb + j) = *(const float4*)(embed_W + (size_t)captions[b * Tt + t] * Ee + e);
        return;
    }
    i4 -= N_EMB4;
    if (i4 < 512) {
        int n = i4 * 4;
        float4 a = *(const float4*)(b_ih + n), b = *(const float4*)(b_hh + n);
        *(float4*)(g_bsum + n) = make_float4(a.x + b.x, a.y + b.y, a.z + b.z, a.w + b.w);
        return;
    }
    i4 -= 512;
    if (i4 < 256) {
        int n = i4 * 4;
        *(float4*)(g_bias_pq + n) = (n < 512) ? *(const float4*)(qz_b + n)
                                              : *(const float4*)(prior_b + n - 512);
        return;
    }
    i4 -= 256;
    if (i4 < 512) { *(float4*)(g_zb + i4 * 4) = make_float4(0, 0, 0, 0); return; }
    i4 -= 512;
    if (i4 < Bb * Hh / 4) { *(float4*)(g_c + i4 * 4) = make_float4(0, 0, 0, 0); return; }
    i4 -= Bb * Hh / 4;
    if (i4 < 2 * Bb * 2048 / 4) {
        int j = i4 * 4;
        if (j < Bb * 2048) *(float4*)(&g_gp[1][0] + j) = make_float4(0, 0, 0, 0);
        else *(float4*)(&g_gp[2][0] + j - Bb * 2048) = make_float4(0, 0, 0, 0);
    }
}
#define PREP_MISC_TOT (N_EMB4 + 512 + 256 + 512 + Bb * Hh / 4 + 2 * Bb * 2048 / 4)

// gates weights: N=2048, K order [e(512), z(256), h(512)], fold [hi|lo|hi]
__global__ void prep_wg_kernel(const float* __restrict__ W_ih, const float* __restrict__ W_hh) {
    int idx = blockIdx.x * blockDim.x + threadIdx.x;
    if (idx >= 2048 * 320) return;
    int n = idx / 320, k = (idx - n * 320) * 4;
    float4 v = (k < 768) ? *(const float4*)(W_ih + (size_t)n * 768 + k)
                         : *(const float4*)(W_hh + (size_t)n * 512 + (k - 768));
    unsigned long long hi, lo;
    cvt4(v, hi, lo);
    int tile = n >> 7, row = n & 127;
    __nv_bfloat16* base = gBg + (size_t)tile * NCH_G * 8192;
    st8(base + ipos(k, row), hi);
    st8(base + ipos(k + 1280, row), lo);
    st8(base + ipos(k + 2560, row), hi);
}

// pq weights: N=1024 (qz 0-511, prior 512-1023 padded over e), K order [e, h]
__global__ void prep_wpq_kernel(const float* __restrict__ qz_W, const float* __restrict__ prior_W) {
    int idx = blockIdx.x * blockDim.x + threadIdx.x;
    if (idx >= 1024 * 256) return;
    int n = idx >> 8, k = (idx & 255) << 2;
    float4 v;
    if (n < 512) v = *(const float4*)(qz_W + (size_t)n * 1024 + k);
    else if (k < 512) v = make_float4(0, 0, 0, 0);
    else v = *(const float4*)(prior_W + (size_t)(n - 512) * 512 + (k - 512));
    unsigned long long hi, lo;
    cvt4(v, hi, lo);
    int tile = n >> 7, row = n & 127;
    __nv_bfloat16* base = gBpq + (size_t)tile * NCH_PQ * 8192;
    st8(base + ipos(k, row), hi);
    st8(base + ipos(k + 1024, row), lo);
    st8(base + ipos(k + 2048, row), hi);
}

// qx weights: N padded to 16128 (84 tiles x 192 rows), K order [z(256), h(512)]
__global__ void prep_wqx_kernel(const float* __restrict__ qx_W) {
    int idx = blockIdx.x * blockDim.x + threadIdx.x;
    if (idx >= 16128 * 192) return;
    int n = idx / 192, k = (idx - n * 192) * 4;
    float4 v = (n < Vv) ? *(const float4*)(qx_W + (size_t)n * 768 + k)
                        : make_float4(0, 0, 0, 0);
    unsigned long long hi, lo;
    cvt4(v, hi, lo);
    int tile = n / QROWS, row = n - tile * QROWS;
    __nv_bfloat16* base = gBqx + (size_t)tile * NCH_QX * QROWS * 64;
    st8(base + ipos192(k, row), hi);
    st8(base + ipos192(k + 768, row), lo);
    st8(base + ipos192(k + 1536, row), hi);
}

// ---------------- fp32 SGEMM (initial step only) ----------------
template <int BM, int BN, int BK, int TM, int TN>
__global__ void sgemm_bt(const float* __restrict__ A, int lda,
                         const float* __restrict__ Bw, int ldb,
                         const float* __restrict__ bias,
                         float* __restrict__ C0, int ldc0, int M, int N, int K) {
    constexpr int THREADS = (BM / TM) * (BN / TN);
    __shared__ float As[BK][BM];
    __shared__ float Bs[BK][BN];
    const int tid = threadIdx.x;
    const int block_m = blockIdx.x * BM;
    const int block_n = blockIdx.y * BN;
    const int tn_ = tid % (BN / TN);
    const int tm_ = tid / (BN / TN);

    float acc[TM][TN];
#pragma unroll
    for (int i = 0; i < TM; i++)
#pragma unroll
        for (int j = 0; j < TN; j++) acc[i][j] = 0.0f;

    constexpr int A_F4 = BM * BK / 4;
    constexpr int B_F4 = BN * BK / 4;
    for (int k0 = 0; k0 < K; k0 += BK) {
#pragma unroll
        for (int i = tid; i < A_F4; i += THREADS) {
            int row = i / (BK / 4), kq = i % (BK / 4);
            float4 v = *(const float4*)(A + (size_t)(block_m + row) * lda + k0 + kq * 4);
            As[kq * 4 + 0][row] = v.x; As[kq * 4 + 1][row] = v.y;
            As[kq * 4 + 2][row] = v.z; As[kq * 4 + 3][row] = v.w;
        }
#pragma unroll
        for (int i = tid; i < B_F4; i += THREADS) {
            int row = i / (BK / 4), kq = i % (BK / 4);
            float4 v = *(const float4*)(Bw + (size_t)(block_n + row) * ldb + k0 + kq * 4);
            Bs[kq * 4 + 0][row] = v.x; Bs[kq * 4 + 1][row] = v.y;
            Bs[kq * 4 + 2][row] = v.z; Bs[kq * 4 + 3][row] = v.w;
        }
        __syncthreads();
#pragma unroll
        for (int kk = 0; kk < BK; kk++) {
            float ra[TM], rb[TN];
#pragma unroll
            for (int i = 0; i < TM; i++) ra[i] = As[kk][tm_ * TM + i];
#pragma unroll
            for (int j = 0; j < TN; j++) rb[j] = Bs[kk][tn_ * TN + j];
#pragma unroll
            for (int i = 0; i < TM; i++)
#pragma unroll
                for (int j = 0; j < TN; j++) acc[i][j] = fmaf(ra[i], rb[j], acc[i][j]);
        }
        __syncthreads();
    }
#pragma unroll
    for (int i = 0; i < TM; i++) {
        int m = block_m + tm_ * TM + i;
#pragma unroll
        for (int j = 0; j < TN; j++) {
            int n = block_n + tn_ * TN + j;
            C0[(size_t)m * ldc0 + n] = acc[i][j] + bias[n];
        }
    }
}

// ---------------- split-bf16 mma GEMM body (templated tile width) ----------------
#define PITCH 144
#define STAGE_B 18432          // A region: 128 rows * 144B

template <int BROWS>
__device__ __forceinline__ void load_stage(uint32_t st, const char* srcA, const char* srcB, int tid) {
#pragma unroll
    for (int j = 0; j < 4; j++) {
        int i = tid + j * 256;
        cpasync16(st + (i >> 3) * PITCH + (i & 7) * 16, srcA + i * 16);
    }
#pragma unroll
    for (int j = 0; j < BROWS / 32; j++) {
        int i = tid + j * 256;
        cpasync16(st + STAGE_B + (i >> 3) * PITCH + (i & 7) * 16, srcB + i * 16);
    }
    asm volatile("cp.async.commit_group;" ::: "memory");
}

// BROWS: B-tile rows (output cols per CTA); NJ2: 16-col groups per warp; GUARD: clip cols to maxN
template <int BROWS, int NJ2, bool GUARD>
__device__ __forceinline__ void gemm_body(
    const __nv_bfloat16* __restrict__ Aimg, const __nv_bfloat16* __restrict__ Bimg,
    int nchunk, const float* __restrict__ bias, float* __restrict__ dst, int ldc,
    int n0, int maxN) {
    constexpr int SSZ = (128 + BROWS) * PITCH;
    constexpr int NJ = 2 * NJ2;
    extern __shared__ __align__(16) char smem[];
    const uint32_t sb = s2u(smem);
    const int tid = threadIdx.x;
    const int wid = tid >> 5;
    const int lane = tid & 31;
    const int warp_m = wid >> 2;
    const int warp_n = wid & 3;

    const char* gA = (const char*)Aimg;
    const char* gB = (const char*)Bimg;

    float acc[4][NJ][4];
#pragma unroll
    for (int i = 0; i < 4; i++)
#pragma unroll
        for (int j = 0; j < NJ; j++)
#pragma unroll
            for (int q = 0; q < 4; q++) acc[i][j][q] = 0.0f;

    const int a_row = lane & 15;
    const int a_coff = (lane >> 4) << 4;
    const int b_row = ((lane >> 4) << 3) | (lane & 7);
    const int b_coff = ((lane >> 3) & 1) << 4;

#pragma unroll
    for (int s = 0; s < 3; s++)
        load_stage<BROWS>(sb + s * SSZ, gA + (size_t)s * 16384,
                          gB + (size_t)s * BROWS * 128, tid);

    int slot = 0;
    for (int c = 0; c < nchunk; c++) {
        asm volatile("cp.async.wait_group 2;" ::: "memory");
        __syncthreads();

        const uint32_t stg = sb + slot * SSZ;
        const uint32_t As = stg;
        const uint32_t Bs = stg + STAGE_B;
#pragma unroll
        for (int ks = 0; ks < 4; ks++) {
            uint32_t a[4][4];
#pragma unroll
            for (int mi = 0; mi < 4; mi++) {
                uint32_t addr = As + (uint32_t)(warp_m * 64 + mi * 16 + a_row) * PITCH +
                                ks * 32 + a_coff;
                ldmatrix_x4(a[mi], addr);
            }
#pragma unroll
            for (int jp = 0; jp < NJ2; jp++) {
                uint32_t b[4];
                uint32_t addr = Bs + (uint32_t)(warp_n * (16 * NJ2) + jp * 16 + b_row) * PITCH +
                                ks * 32 + b_coff;
                ldmatrix_x4(b, addr);
#pragma unroll
                for (int mi = 0; mi < 4; mi++) {
                    mma16816(acc[mi][jp * 2 + 0], a[mi], b[0], b[1]);
                    mma16816(acc[mi][jp * 2 + 1], a[mi], b[2], b[3]);
                }
            }
        }
        __syncthreads();
        if (c + 3 < nchunk)
            load_stage<BROWS>(sb + slot * SSZ, gA + (size_t)(c + 3) * 16384,
                              gB + (size_t)(c + 3) * BROWS * 128, tid);
        else
            asm volatile("cp.async.commit_group;" ::: "memory");
        slot = (slot == 2) ? 0 : slot + 1;
    }

    const int g = lane >> 2, tq = lane & 3;
#pragma unroll
    for (int mi = 0; mi < 4; mi++) {
        int row = warp_m * 64 + mi * 16 + g;
#pragma unroll
        for (int nj = 0; nj < NJ; nj++) {
            int col = n0 + warp_n * (16 * NJ2) + nj * 8 + 2 * tq;
            if (GUARD && col >= maxN) continue;
            float b0 = bias[col], b1 = bias[col + 1];
            float2 v0 = make_float2(acc[mi][nj][0] + b0, acc[mi][nj][1] + b1);
            float2 v1 = make_float2(acc[mi][nj][2] + b0, acc[mi][nj][3] + b1);
            *(float2*)(dst + (size_t)row * ldc + col) = v0;
            *(float2*)(dst + (size_t)(row + 8) * ldc + col) = v1;
        }
    }
}

#define SM128 (3 * (128 + 128) * PITCH)   // 110592
#define SMQX  (3 * (128 + QROWS) * PITCH) // 138240

// pq: 48 CTAs = 6 K-segs x 8 N-tiles -> partials
__global__ void __launch_bounds__(256) pq_kernel() {
    int seg = blockIdx.x >> 3, tile = blockIdx.x & 7;
    gemm_body<128, 2, false>(gApq + (size_t)seg * 8 * 8192,
                             gBpq + ((size_t)tile * NCH_PQ + seg * 8) * 8192,
                             8, g_zb, g_pqp[seg], 1024, tile << 7, 1 << 30);
}

// gates: 48 CTAs = 3 K-segs x 16 N-tiles -> partials
__global__ void __launch_bounds__(256) gates_kernel() {
    int seg = blockIdx.x >> 4, tile = blockIdx.x & 15;
    gemm_body<128, 2, false>(gAg + (size_t)seg * 20 * 8192,
                             gBg + ((size_t)tile * NCH_G + seg * 20) * 8192,
                             20, g_zb, g_gp[seg], 2048, tile << 7, 1 << 30);
}

// qx: 84 CTAs of 128x192, parity-selected A image
__global__ void __launch_bounds__(256) qx_kernel(const float* __restrict__ qx_b,
                                                 float* __restrict__ dst, int par) {
    gemm_body<QROWS, 3, true>(gAqx2[par],
                              gBqx + (size_t)blockIdx.x * NCH_QX * QROWS * 64,
                              NCH_QX, qx_b, dst, Vv, blockIdx.x * QROWS, Vv);
}

// build2: reduce 6 pq partials -> 4 outputs; z = noise*qsig+qmu -> z-images (vec4)
__global__ void build2_kernel(const float* __restrict__ noise, float* __restrict__ out,
                              int t, int par) {
    int i4 = blockIdx.x * 256 + threadIdx.x;
    if (i4 >= Bb * Ll / 4) return;
    int m = i4 >> 6;
    int l = (i4 & 63) << 2;
    const int r = m * 1024;
#define SUM6(off) ({ \
    float4 s = *(const float4*)(g_bias_pq + (off)); \
    _Pragma("unroll") \
    for (int sg = 0; sg < 6; sg++) { \
        float4 a = *(const float4*)(&g_pqp[sg][0] + r + (off)); \
        s.x += a.x; s.y += a.y; s.z += a.z; s.w += a.w; \
    } s; })
    float4 qmu = SUM6(l);
    float4 qsig = SUM6(256 + l);
    float4 pmu = SUM6(512 + l);
    float4 psig = SUM6(768 + l);
#undef SUM6
    size_t o = ((size_t)t * Bb + m) * Ll + l;
    *(float4*)(out + OFF_QMU + o) = qmu;
    *(float4*)(out + OFF_QSIG + o) = qsig;
    *(float4*)(out + OFF_PMU + o) = pmu;
    *(float4*)(out + OFF_PSIG + o) = psig;
    float4 nz = *(const float4*)(noise + ((size_t)m * Tt + t) * Ll + l);
    float4 z = make_float4(nz.x * qsig.x + qmu.x, nz.y * qsig.y + qmu.y,
                           nz.z * qsig.z + qmu.z, nz.w * qsig.w + qmu.w);
    unsigned long long hi, lo;
    cvt4(z, hi, lo);
    int kg = 512 + l;
    st8(gAg + ipos(kg, m), hi);
    st8(gAg + ipos(kg + 1280, m), hi);
    st8(gAg + ipos(kg + 2560, m), lo);
    __nv_bfloat16* aqx = gAqx2[par];
    st8(aqx + ipos(l, m), hi);
    st8(aqx + ipos(l + 768, m), hi);
    st8(aqx + ipos(l + 1536, m), lo);
}

// epilogue: lstm-reduce + h-images (vb<32) + e-images for t_next (32<=vb<64); vec4
__global__ void epilogue_kernel(int t_next) {
    int vb = blockIdx.x, tid = threadIdx.x;
    int par = t_next & 1;
    if (vb < 32) {
        int i4 = vb * 512 + tid;
        int b = i4 >> 7;
        int n = (i4 & 127) << 2;
        const int r = b * 2048;
#define GSUM(off) ({ \
        float4 a = *(const float4*)(&g_gp[0][0] + r + (off)); \
        float4 x = *(const float4*)(&g_gp[1][0] + r + (off)); \
        float4 c = *(const float4*)(&g_gp[2][0] + r + (off)); \
        float4 d = *(const float4*)(g_bsum + (off)); \
        make_float4(a.x + x.x + c.x + d.x, a.y + x.y + c.y + d.y, \
                    a.z + x.z + c.z + d.z, a.w + x.w + c.w + d.w); })
        float4 gi = GSUM(n);
        float4 gf = GSUM(512 + n);
        float4 gg = GSUM(1024 + n);
        float4 go = GSUM(1536 + n);
#undef GSUM
        float4 co = *(const float4*)(g_c + b * 512 + n);
        float4 cn, h;
        cn.x = sigf(gf.x) * co.x + sigf(gi.x) * tanhf(gg.x);
        cn.y = sigf(gf.y) * co.y + sigf(gi.y) * tanhf(gg.y);
        cn.z = sigf(gf.z) * co.z + sigf(gi.z) * tanhf(gg.z);
        cn.w = sigf(gf.w) * co.w + sigf(gi.w) * tanhf(gg.w);
        h.x = sigf(go.x) * tanhf(cn.x);
        h.y = sigf(go.y) * tanhf(cn.y);
        h.z = sigf(go.z) * tanhf(cn.z);
        h.w = sigf(go.w) * tanhf(cn.w);
        *(float4*)(g_c + b * 512 + n) = cn;
        *(float4*)(g_h + b * 512 + n) = h;
        unsigned long long hi, lo;
        cvt4(h, hi, lo);
        int k = 512 + n;
        st8(gApq + ipos(k, b), hi);
        st8(gApq + ipos(k + 1024, b), hi);
        st8(gApq + ipos(k + 2048, b), lo);
        int kg = 768 + n;
        st8(gAg + ipos(kg, b), hi);
        st8(gAg + ipos(kg + 1280, b), hi);
        st8(gAg + ipos(kg + 2560, b), lo);
        __nv_bfloat16* aqx = gAqx2[par];
        int kq = 256 + n;
        st8(aqx + ipos(kq, b), hi);
        st8(aqx + ipos(kq + 768, b), hi);
        st8(aqx + ipos(kq + 1536, b), lo);
    } else {
        if (t_next >= Tt) return;
        int i4 = (vb - 32) * 512 + tid;
        int m = i4 >> 7;
        int e = (i4 & 127) << 2;
        float4 v = *(const float4*)(g_emb + (((size_t)t_next * Bb + m) << 9) + e);
        unsigned long long hi, lo;
        cvt4(v, hi, lo);
        st8(gApq + ipos(e, m), hi);
        st8(gApq + ipos(e + 1024, m), hi);
        st8(gApq + ipos(e + 2048, m), lo);
        st8(gAg + ipos(e, m), hi);
        st8(gAg + ipos(e + 1280, m), hi);
        st8(gAg + ipos(e + 2560, m), lo);
    }
}

// In-place log_softmax over rows of length V
__global__ void softmax_kernel(float* __restrict__ base) {
    float* x = base + (size_t)blockIdx.x * Vv;
    __shared__ float sred[16];
    __shared__ float sval;
    const int tid = threadIdx.x;
    float m = -3.4e38f;
    for (int i = tid; i < Vv; i += 512) m = fmaxf(m, x[i]);
#pragma unroll
    for (int o = 16; o; o >>= 1) m = fmaxf(m, __shfl_xor_sync(0xffffffffu, m, o));
    if ((tid & 31) == 0) sred[tid >> 5] = m;
    __syncthreads();
    if (tid < 32) {
        float v = (tid < 16) ? sred[tid] : -3.4e38f;
#pragma unroll
        for (int o = 8; o; o >>= 1) v = fmaxf(v, __shfl_xor_sync(0xffffffffu, v, o));
        if (tid == 0) sval = v;
    }
    __syncthreads();
    m = sval;
    float s = 0.0f;
    for (int i = tid; i < Vv; i += 512) s += expf(x[i] - m);
#pragma unroll
    for (int o = 16; o; o >>= 1) s += __shfl_xor_sync(0xffffffffu, s, o);
    __syncthreads();
    if ((tid & 31) == 0) sred[tid >> 5] = s;
    __syncthreads();
    if (tid < 32) {
        float v = (tid < 16) ? sred[tid] : 0.0f;
#pragma unroll
        for (int o = 8; o; o >>= 1) v += __shfl_xor_sync(0xffffffffu, v, o);
        if (tid == 0) sval = m + logf(v);
    }
    __syncthreads();
    float lz = sval;
    for (int i = tid; i < Vv; i += 512) x[i] -= lz;
}

extern "C" void kernel_launch(void* const* d_in, const int* in_sizes, int n_in,
                              void* d_out, int out_size) {
    const float* features = (const float*)d_in[0];
    const int* captions = (const int*)d_in[1];
    const float* noise   = (const float*)d_in[3];
    const float* embed_W = (const float*)d_in[4];
    const float* W_ih    = (const float*)d_in[5];
    const float* W_hh    = (const float*)d_in[6];
    const float* b_ih    = (const float*)d_in[7];
    const float* b_hh    = (const float*)d_in[8];
    const float* qz_W    = (const float*)d_in[9];
    const float* qz_b    = (const float*)d_in[10];
    const float* prior_W = (const float*)d_in[11];
    const float* prior_b = (const float*)d_in[12];
    const float* qx_W    = (const float*)d_in[13];
    const float* qx_b    = (const float*)d_in[14];
    float* out = (float*)d_out;

    static cudaStream_t s1 = nullptr, s2 = nullptr;
    static cudaEvent_t evZ = nullptr, evQ0 = nullptr, evQ1 = nullptr, evJ1 = nullptr, evJ2 = nullptr;
    if (s1 == nullptr) {
        cudaStreamCreateWithFlags(&s1, cudaStreamNonBlocking);
        cudaStreamCreateWithFlags(&s2, cudaStreamNonBlocking);
        cudaEventCreateWithFlags(&evZ, cudaEventDisableTiming);
        cudaEventCreateWithFlags(&evQ0, cudaEventDisableTiming);
        cudaEventCreateWithFlags(&evQ1, cudaEventDisableTiming);
        cudaEventCreateWithFlags(&evJ1, cudaEventDisableTiming);
        cudaEventCreateWithFlags(&evJ2, cudaEventDisableTiming);
    }

    float *pzb, *pgp0;
    cudaGetSymbolAddress((void**)&pzb, g_zb);
    cudaGetSymbolAddress((void**)&pgp0, g_gp);

    cudaFuncSetAttribute(pq_kernel, cudaFuncAttributeMaxDynamicSharedMemorySize, SM128);
    cudaFuncSetAttribute(gates_kernel, cudaFuncAttributeMaxDynamicSharedMemorySize, SM128);
    cudaFuncSetAttribute(qx_kernel, cudaFuncAttributeMaxDynamicSharedMemorySize, SMQX);

    // one-time prep
    prep_misc_kernel<<<(PREP_MISC_TOT + 255) / 256, 256>>>(b_ih, b_hh, qz_b, prior_b,
                                                           embed_W, captions);
    prep_wg_kernel<<<(2048 * 320 + 255) / 256, 256>>>(W_ih, W_hh);
    prep_wpq_kernel<<<(1024 * 256 + 255) / 256, 256>>>(qz_W, prior_W);
    prep_wqx_kernel<<<(16128 * 192 + 255) / 256, 256>>>(qx_W);

    // initial LSTM step
    {
        dim3 grid(Bb / 32, 2048 / 64);
        sgemm_bt<32, 64, 8, 4, 4><<<grid, 128>>>(features, Ee, W_ih, 768, pzb,
                                                 pgp0, 2048, Bb, 2048, Ee);
        epilogue_kernel<<<64, 512>>>(0);
    }

    for (int t = 0; t < Tt; t++) {
        pq_kernel<<<48, 256, SM128>>>();
        build2_kernel<<<32, 256>>>(noise, out, t, t & 1);
        cudaEventRecord(evZ, 0);
        cudaStreamWaitEvent(s1, evZ, 0);
        float* qx_dst = out + OFF_QX + (size_t)t * Bb * Vv;
        qx_kernel<<<NT_QX, 256, SMQX, s1>>>(qx_b, qx_dst, t & 1);
        cudaEvent_t eq = (t & 1) ? evQ1 : evQ0;
        cudaEventRecord(eq, s1);
        cudaStreamWaitEvent(s2, eq, 0);
        softmax_kernel<<<128, 512, 0, s2>>>(qx_dst);
        gates_kernel<<<48, 256, SM128>>>();
        if (t >= 1) cudaStreamWaitEvent(0, (t & 1) ? evQ0 : evQ1, 0);  // qx(t-1) done
        epilogue_kernel<<<64, 512>>>(t + 1);
    }

    cudaEventRecord(evJ1, s1);
    cudaStreamWaitEvent(0, evJ1, 0);
    cudaEventRecord(evJ2, s2);
    cudaStreamWaitEvent(0, evJ2, 0);
}

// round 8
// speedup vs baseline: 6.5423x; 1.1461x over previous
#include <cuda_runtime.h>
#include <cuda_bf16.h>
#include <math.h>
#include <stdint.h>

// Problem constants
#define Bb 128
#define Tt 32
#define Ee 512
#define Hh 512
#define Ll 256
#define Vv 16000

#define NCH_G  60      // gates: K2=3840 (folded)
#define NCH_PQ 48      // pq: K2=3072 (folded)
#define NT_G   16
#define NT_QX  84      // qx tiles of 192 cols: 84*192 = 16128
#define QROWS  192
#define QCH    12      // qx chunks of 64 over K=768 (unfolded hi/lo)

// Output layout: p_mus, p_sigmas, q_mus, q_sigmas, q_xs
#define OFF_PMU  ((size_t)0)
#define OFF_PSIG ((size_t)Tt * Bb * Ll)
#define OFF_QMU  ((size_t)2 * Tt * Bb * Ll)
#define OFF_QSIG ((size_t)3 * Tt * Bb * Ll)
#define OFF_QX   ((size_t)4 * Tt * Bb * Ll)

// ---------------- device scratch ----------------
__device__ float g_emb[Tt * Bb * Ee];
__device__ float g_bsum[4 * Hh];
__device__ float g_bias_pq[1024];
__device__ float g_zb[2048];
__device__ float g_h[Bb * Hh];
__device__ float g_c[Bb * Hh];
__device__ float g_pqp[6][Bb * 1024];
__device__ float g_gp[3][Bb * 2048];
__device__ int g_ctrA[Tt];
__device__ int g_ctrB[Tt + 1];

// Weight images (once)
__device__ __align__(16) __nv_bfloat16 gBg[(size_t)NT_G * NCH_G * 8192];
__device__ __align__(16) __nv_bfloat16 gBpq[(size_t)8 * NCH_PQ * 8192];
// qx B: [tile 84][chunk 12][hi 192x64 | lo 192x64]
__device__ __align__(16) __nv_bfloat16 gBqx[(size_t)NT_QX * QCH * 2 * QROWS * 64];
// A images: pq/gates folded single; qx triple-buffered [chunk 12][hi 128x64 | lo 128x64]
__device__ __align__(16) __nv_bfloat16 gAg[NCH_G * 8192];
__device__ __align__(16) __nv_bfloat16 gApq[NCH_PQ * 8192];
__device__ __align__(16) __nv_bfloat16 gAqx3[3][QCH * 16384];

__device__ __forceinline__ float sigf(float x) { return 1.0f / (1.0f + expf(-x)); }

__device__ __forceinline__ uint32_t s2u(const void* p) {
    uint32_t a;
    asm("{ .reg .u64 t; cvta.to.shared.u64 t, %1; cvt.u32.u64 %0, t; }" : "=r"(a) : "l"(p));
    return a;
}
__device__ __forceinline__ void cpasync16(uint32_t dst, const void* src) {
    asm volatile("cp.async.cg.shared.global [%0], [%1], 16;"
                 :: "r"(dst), "l"(__cvta_generic_to_global(src)) : "memory");
}
__device__ __forceinline__ void ldmatrix_x4(uint32_t* r, uint32_t addr) {
    asm volatile("ldmatrix.sync.aligned.m8n8.x4.shared.b16 {%0,%1,%2,%3}, [%4];"
                 : "=r"(r[0]), "=r"(r[1]), "=r"(r[2]), "=r"(r[3]) : "r"(addr));
}
__device__ __forceinline__ void mma16816(float* c, const uint32_t* a, uint32_t b0, uint32_t b1) {
    asm volatile(
        "mma.sync.aligned.m16n8k16.row.col.f32.bf16.bf16.f32 "
        "{%0,%1,%2,%3}, {%4,%5,%6,%7}, {%8,%9}, {%0,%1,%2,%3};"
        : "+f"(c[0]), "+f"(c[1]), "+f"(c[2]), "+f"(c[3])
        : "r"(a[0]), "r"(a[1]), "r"(a[2]), "r"(a[3]), "r"(b0), "r"(b1));
}
__device__ __forceinline__ size_t ipos(int k2, int m) {       // folded 128-row images
    return (((size_t)(k2 >> 6) * 128 + m) << 6) + (k2 & 63);
}
__device__ __forceinline__ size_t qpos(int k, int m, int sel) { // qx A image
    return (size_t)(k >> 6) * 16384 + sel * 8192 + m * 64 + (k & 63);
}
__device__ __forceinline__ unsigned long long pk4(__nv_bfloat16 a, __nv_bfloat16 b,
                                                  __nv_bfloat16 c, __nv_bfloat16 d) {
    union { __nv_bfloat16 h[4]; unsigned long long u; } t;
    t.h[0] = a; t.h[1] = b; t.h[2] = c; t.h[3] = d;
    return t.u;
}
__device__ __forceinline__ void cvt4(float4 v, unsigned long long& hi, unsigned long long& lo) {
    __nv_bfloat16 h0 = __float2bfloat16(v.x), h1 = __float2bfloat16(v.y);
    __nv_bfloat16 h2 = __float2bfloat16(v.z), h3 = __float2bfloat16(v.w);
    hi = pk4(h0, h1, h2, h3);
    lo = pk4(__float2bfloat16(v.x - __bfloat162float(h0)),
             __float2bfloat16(v.y - __bfloat162float(h1)),
             __float2bfloat16(v.z - __bfloat162float(h2)),
             __float2bfloat16(v.w - __bfloat162float(h3)));
}
__device__ __forceinline__ void st8(__nv_bfloat16* p, unsigned long long v) {
    *(unsigned long long*)p = v;
}
// grid barrier across 48 co-resident CTAs (per-step counter slot, prep-zeroed)
__device__ __forceinline__ void grid_barrier48(int* ctr) {
    __threadfence();
    __syncthreads();
    if (threadIdx.x == 0) {
        atomicAdd(ctr, 1);
        while (atomicAdd(ctr, 0) < 48) { }
    }
    __syncthreads();
}

// ---------------- one-time prep ----------------
#define N_EMB4 (Tt * Bb * Ee / 4)
#define GAG_Z  (NCH_G * 8192 * 2 / 16)   // gAg bytes / 16
__global__ void prep_misc_kernel(const float* __restrict__ b_ih, const float* __restrict__ b_hh,
                                 const float* __restrict__ qz_b, const float* __restrict__ prior_b,
                                 const float* __restrict__ embed_W, const int* __restrict__ captions) {
    int i4 = blockIdx.x * blockDim.x + threadIdx.x;
    if (i4 < N_EMB4) {
        int j = i4 * 4;
        int tb = j >> 9, e = j & 511;
        int t = tb / Bb, b = tb % Bb;
        *(float4*)(g_emb + j) = *(const float4*)(embed_W + (size_t)captions[b * Tt + t] * Ee + e);
        return;
    }
    i4 -= N_EMB4;
    if (i4 < 512) {
        int n = i4 * 4;
        float4 a = *(const float4*)(b_ih + n), b = *(const float4*)(b_hh + n);
        *(float4*)(g_bsum + n) = make_float4(a.x + b.x, a.y + b.y, a.z + b.z, a.w + b.w);
        return;
    }
    i4 -= 512;
    if (i4 < 256) {
        int n = i4 * 4;
        *(float4*)(g_bias_pq + n) = (n < 512) ? *(const float4*)(qz_b + n)
                                              : *(const float4*)(prior_b + n - 512);
        return;
    }
    i4 -= 256;
    if (i4 < 512) { *(float4*)(g_zb + i4 * 4) = make_float4(0, 0, 0, 0); return; }
    i4 -= 512;
    if (i4 < Bb * Hh / 4) { *(float4*)(g_c + i4 * 4) = make_float4(0, 0, 0, 0); return; }
    i4 -= Bb * Hh / 4;
    if (i4 < GAG_Z) { *(float4*)((char*)gAg + (size_t)i4 * 16) = make_float4(0, 0, 0, 0); return; }
    i4 -= GAG_Z;
    if (i4 < Tt + Tt + 1) {
        if (i4 < Tt) g_ctrA[i4] = 0;
        else g_ctrB[i4 - Tt] = 0;
    }
}
#define PREP_MISC_TOT (N_EMB4 + 512 + 256 + 512 + Bb * Hh / 4 + GAG_Z + 2 * Tt + 1)

// gates weights: N=2048, K order [e(512), z(256), h(512)], fold [hi|lo|hi]
__global__ void prep_wg_kernel(const float* __restrict__ W_ih, const float* __restrict__ W_hh) {
    int idx = blockIdx.x * blockDim.x + threadIdx.x;
    if (idx >= 2048 * 320) return;
    int n = idx / 320, k = (idx - n * 320) * 4;
    float4 v = (k < 768) ? *(const float4*)(W_ih + (size_t)n * 768 + k)
                         : *(const float4*)(W_hh + (size_t)n * 512 + (k - 768));
    unsigned long long hi, lo;
    cvt4(v, hi, lo);
    int tile = n >> 7, row = n & 127;
    __nv_bfloat16* base = gBg + (size_t)tile * NCH_G * 8192;
    st8(base + ipos(k, row), hi);
    st8(base + ipos(k + 1280, row), lo);
    st8(base + ipos(k + 2560, row), hi);
}

// pq weights: N=1024 (qz 0-511, prior 512-1023 padded over e), K order [e, h]
__global__ void prep_wpq_kernel(const float* __restrict__ qz_W, const float* __restrict__ prior_W) {
    int idx = blockIdx.x * blockDim.x + threadIdx.x;
    if (idx >= 1024 * 256) return;
    int n = idx >> 8, k = (idx & 255) << 2;
    float4 v;
    if (n < 512) v = *(const float4*)(qz_W + (size_t)n * 1024 + k);
    else if (k < 512) v = make_float4(0, 0, 0, 0);
    else v = *(const float4*)(prior_W + (size_t)(n - 512) * 512 + (k - 512));
    unsigned long long hi, lo;
    cvt4(v, hi, lo);
    int tile = n >> 7, row = n & 127;
    __nv_bfloat16* base = gBpq + (size_t)tile * NCH_PQ * 8192;
    st8(base + ipos(k, row), hi);
    st8(base + ipos(k + 1024, row), lo);
    st8(base + ipos(k + 2048, row), hi);
}

// qx weights unfolded: per tile/chunk: [hi 192x64 | lo 192x64]
__global__ void prep_wqx_kernel(const float* __restrict__ qx_W) {
    int idx = blockIdx.x * blockDim.x + threadIdx.x;
    if (idx >= 16128 * 192) return;
    int n = idx / 192, k = (idx - n * 192) * 4;
    float4 v = (n < Vv) ? *(const float4*)(qx_W + (size_t)n * 768 + k)
                        : make_float4(0, 0, 0, 0);
    unsigned long long hi, lo;
    cvt4(v, hi, lo);
    int tile = n / QROWS, row = n - tile * QROWS;
    __nv_bfloat16* base = gBqx + (size_t)tile * (QCH * 2 * QROWS * 64);
    size_t off = (size_t)(k >> 6) * (2 * QROWS * 64) + row * 64 + (k & 63);
    st8(base + off, hi);
    st8(base + off + QROWS * 64, lo);
}

// features A-image (initial step): e-section of gAg (z,h sections pre-zeroed)
__global__ void build_feat_kernel(const float* __restrict__ features) {
    int i4 = blockIdx.x * 512 + threadIdx.x;
    int m = i4 >> 7;
    int e = (i4 & 127) << 2;
    float4 v = *(const float4*)(features + (size_t)m * 512 + e);
    unsigned long long hi, lo;
    cvt4(v, hi, lo);
    st8(gAg + ipos(e, m), hi);
    st8(gAg + ipos(e + 1280, m), hi);
    st8(gAg + ipos(e + 2560, m), lo);
}

// ---------------- folded split-bf16 mma GEMM body (pq/gates) ----------------
#define PITCH 144
#define STAGE_B 18432
#define SSZ128 ((128 + 128) * PITCH)
#define SM128 (3 * SSZ128)

__device__ __forceinline__ void load_stage(uint32_t st, const char* srcA, const char* srcB, int tid) {
#pragma unroll
    for (int j = 0; j < 4; j++) {
        int i = tid + j * 256;
        cpasync16(st + (i >> 3) * PITCH + (i & 7) * 16, srcA + i * 16);
    }
#pragma unroll
    for (int j = 0; j < 4; j++) {
        int i = tid + j * 256;
        cpasync16(st + STAGE_B + (i >> 3) * PITCH + (i & 7) * 16, srcB + i * 16);
    }
    asm volatile("cp.async.commit_group;" ::: "memory");
}

__device__ __forceinline__ void gemm_body(
    const __nv_bfloat16* __restrict__ Aimg, const __nv_bfloat16* __restrict__ Bimg,
    int nchunk, float* __restrict__ dst, int ldc, int n0) {
    extern __shared__ __align__(16) char smem[];
    const uint32_t sb = s2u(smem);
    const int tid = threadIdx.x;
    const int wid = tid >> 5;
    const int lane = tid & 31;
    const int warp_m = wid >> 2;
    const int warp_n = wid & 3;

    const char* gA = (const char*)Aimg;
    const char* gB = (const char*)Bimg;

    float acc[4][4][4];
#pragma unroll
    for (int i = 0; i < 4; i++)
#pragma unroll
        for (int j = 0; j < 4; j++)
#pragma unroll
            for (int q = 0; q < 4; q++) acc[i][j][q] = 0.0f;

    const int a_row = lane & 15;
    const int a_coff = (lane >> 4) << 4;
    const int b_row = ((lane >> 4) << 3) | (lane & 7);
    const int b_coff = ((lane >> 3) & 1) << 4;

#pragma unroll
    for (int s = 0; s < 3; s++)
        load_stage(sb + s * SSZ128, gA + (size_t)s * 16384, gB + (size_t)s * 16384, tid);

    int slot = 0;
    for (int c = 0; c < nchunk; c++) {
        asm volatile("cp.async.wait_group 2;" ::: "memory");
        __syncthreads();

        const uint32_t As = sb + slot * SSZ128;
        const uint32_t Bs = As + STAGE_B;
#pragma unroll
        for (int ks = 0; ks < 4; ks++) {
            uint32_t a[4][4];
#pragma unroll
            for (int mi = 0; mi < 4; mi++)
                ldmatrix_x4(a[mi], As + (uint32_t)(warp_m * 64 + mi * 16 + a_row) * PITCH +
                                    ks * 32 + a_coff);
#pragma unroll
            for (int jp = 0; jp < 2; jp++) {
                uint32_t b[4];
                ldmatrix_x4(b, Bs + (uint32_t)(warp_n * 32 + jp * 16 + b_row) * PITCH +
                                ks * 32 + b_coff);
#pragma unroll
                for (int mi = 0; mi < 4; mi++) {
                    mma16816(acc[mi][jp * 2 + 0], a[mi], b[0], b[1]);
                    mma16816(acc[mi][jp * 2 + 1], a[mi], b[2], b[3]);
                }
            }
        }
        __syncthreads();
        if (c + 3 < nchunk)
            load_stage(sb + slot * SSZ128, gA + (size_t)(c + 3) * 16384,
                       gB + (size_t)(c + 3) * 16384, tid);
        else
            asm volatile("cp.async.commit_group;" ::: "memory");
        slot = (slot == 2) ? 0 : slot + 1;
    }

    const int g = lane >> 2, tq = lane & 3;
#pragma unroll
    for (int mi = 0; mi < 4; mi++) {
        int row = warp_m * 64 + mi * 16 + g;
#pragma unroll
        for (int nj = 0; nj < 4; nj++) {
            int col = n0 + warp_n * 32 + nj * 8 + 2 * tq;
            float2 v0 = make_float2(acc[mi][nj][0], acc[mi][nj][1]);
            float2 v1 = make_float2(acc[mi][nj][2], acc[mi][nj][3]);
            *(float2*)(dst + (size_t)row * ldc + col) = v0;
            *(float2*)(dst + (size_t)(row + 8) * ldc + col) = v1;
        }
    }
}

// ---------------- fused pq GEMM + reduce/z/outputs (48 CTAs) ----------------
__global__ void __launch_bounds__(256) pqz_kernel(const float* __restrict__ noise,
                                                  float* __restrict__ out, int t) {
    int seg = blockIdx.x >> 3, tile = blockIdx.x & 7;
    gemm_body(gApq + (size_t)seg * 8 * 8192,
              gBpq + ((size_t)tile * NCH_PQ + seg * 8) * 8192,
              8, g_pqp[seg], 1024, tile << 7);

    grid_barrier48(&g_ctrA[t]);

    int par = t % 3;
    __nv_bfloat16* aqx = gAqx3[par];
    for (int i4 = blockIdx.x * 256 + threadIdx.x; i4 < Bb * Ll / 4; i4 += 48 * 256) {
        int m = i4 >> 6;
        int l = (i4 & 63) << 2;
        const int r = m * 1024;
#define SUM6(off) ({ \
        float4 s = *(const float4*)(g_bias_pq + (off)); \
        _Pragma("unroll") \
        for (int sg = 0; sg < 6; sg++) { \
            float4 a = *(const float4*)(&g_pqp[sg][0] + r + (off)); \
            s.x += a.x; s.y += a.y; s.z += a.z; s.w += a.w; \
        } s; })
        float4 qmu = SUM6(l);
        float4 qsig = SUM6(256 + l);
        float4 pmu = SUM6(512 + l);
        float4 psig = SUM6(768 + l);
#undef SUM6
        size_t o = ((size_t)t * Bb + m) * Ll + l;
        *(float4*)(out + OFF_QMU + o) = qmu;
        *(float4*)(out + OFF_QSIG + o) = qsig;
        *(float4*)(out + OFF_PMU + o) = pmu;
        *(float4*)(out + OFF_PSIG + o) = psig;
        float4 nz = *(const float4*)(noise + ((size_t)m * Tt + t) * Ll + l);
        float4 z = make_float4(nz.x * qsig.x + qmu.x, nz.y * qsig.y + qmu.y,
                               nz.z * qsig.z + qmu.z, nz.w * qsig.w + qmu.w);
        unsigned long long hi, lo;
        cvt4(z, hi, lo);
        int kg = 512 + l;
        st8(gAg + ipos(kg, m), hi);
        st8(gAg + ipos(kg + 1280, m), hi);
        st8(gAg + ipos(kg + 2560, m), lo);
        st8(aqx + qpos(l, m, 0), hi);
        st8(aqx + qpos(l, m, 1), lo);
    }
}

// ---------------- fused gates GEMM + LSTM + h/e-images (48 CTAs) ----------------
__global__ void __launch_bounds__(256) gatesepi_kernel(int t_next) {
    int seg = blockIdx.x >> 4, tile = blockIdx.x & 15;
    gemm_body(gAg + (size_t)seg * 20 * 8192,
              gBg + ((size_t)tile * NCH_G + seg * 20) * 8192,
              20, g_gp[seg], 2048, tile << 7);

    grid_barrier48(&g_ctrB[t_next]);

    int par = t_next % 3;
    __nv_bfloat16* aqx = gAqx3[par];
    for (int i4 = blockIdx.x * 256 + threadIdx.x; i4 < Bb * Hh / 4; i4 += 48 * 256) {
        int b = i4 >> 7;
        int n = (i4 & 127) << 2;
        const int r = b * 2048;
#define GSUM(off) ({ \
        float4 a = *(const float4*)(&g_gp[0][0] + r + (off)); \
        float4 x = *(const float4*)(&g_gp[1][0] + r + (off)); \
        float4 c = *(const float4*)(&g_gp[2][0] + r + (off)); \
        float4 d = *(const float4*)(g_bsum + (off)); \
        make_float4(a.x + x.x + c.x + d.x, a.y + x.y + c.y + d.y, \
                    a.z + x.z + c.z + d.z, a.w + x.w + c.w + d.w); })
        float4 gi = GSUM(n);
        float4 gf = GSUM(512 + n);
        float4 gg = GSUM(1024 + n);
        float4 go = GSUM(1536 + n);
#undef GSUM
        float4 co = *(const float4*)(g_c + b * 512 + n);
        float4 cn, h;
        cn.x = sigf(gf.x) * co.x + sigf(gi.x) * tanhf(gg.x);
        cn.y = sigf(gf.y) * co.y + sigf(gi.y) * tanhf(gg.y);
        cn.z = sigf(gf.z) * co.z + sigf(gi.z) * tanhf(gg.z);
        cn.w = sigf(gf.w) * co.w + sigf(gi.w) * tanhf(gg.w);
        h.x = sigf(go.x) * tanhf(cn.x);
        h.y = sigf(go.y) * tanhf(cn.y);
        h.z = sigf(go.z) * tanhf(cn.z);
        h.w = sigf(go.w) * tanhf(cn.w);
        *(float4*)(g_c + b * 512 + n) = cn;
        *(float4*)(g_h + b * 512 + n) = h;
        unsigned long long hi, lo;
        cvt4(h, hi, lo);
        int k = 512 + n;
        st8(gApq + ipos(k, b), hi);
        st8(gApq + ipos(k + 1024, b), hi);
        st8(gApq + ipos(k + 2048, b), lo);
        int kg = 768 + n;
        st8(gAg + ipos(kg, b), hi);
        st8(gAg + ipos(kg + 1280, b), hi);
        st8(gAg + ipos(kg + 2560, b), lo);
        int kq = 256 + n;
        st8(aqx + qpos(kq, b, 0), hi);
        st8(aqx + qpos(kq, b, 1), lo);
    }
    if (t_next < Tt) {
        const float* src = g_emb + (((size_t)t_next * Bb) << 9);
        for (int i4 = blockIdx.x * 256 + threadIdx.x; i4 < Bb * Ee / 4; i4 += 48 * 256) {
            int m = i4 >> 7;
            int e = (i4 & 127) << 2;
            float4 v = *(const float4*)(src + ((size_t)m << 9) + e);
            unsigned long long hi, lo;
            cvt4(v, hi, lo);
            st8(gApq + ipos(e, m), hi);
            st8(gApq + ipos(e + 1024, m), hi);
            st8(gApq + ipos(e + 2048, m), lo);
            st8(gAg + ipos(e, m), hi);
            st8(gAg + ipos(e + 1280, m), hi);
            st8(gAg + ipos(e + 2560, m), lo);
        }
    }
}

// ---------------- unfolded qx GEMM (84 CTAs, 128x192, 2-stage) ----------------
#define STAGE_A2 (256 * PITCH)             // 36864 (Ahi 128 rows + Alo 128 rows)
#define QSTG ((256 + 384) * PITCH)         // 92160
#define SMQX (2 * QSTG)                    // 184320

__device__ __forceinline__ void load_stage_qx(uint32_t st, const char* srcA, const char* srcB,
                                              int tid) {
#pragma unroll
    for (int j = 0; j < 8; j++) {          // A: 32KB (hi 128x128B, lo 128x128B)
        int i = tid + j * 256;
        cpasync16(st + (i >> 3) * PITCH + (i & 7) * 16, srcA + i * 16);
    }
#pragma unroll
    for (int j = 0; j < 12; j++) {         // B: 48KB (hi 192x128B, lo 192x128B)
        int i = tid + j * 256;
        cpasync16(st + STAGE_A2 + (i >> 3) * PITCH + (i & 7) * 16, srcB + i * 16);
    }
    asm volatile("cp.async.commit_group;" ::: "memory");
}

__global__ void __launch_bounds__(256) qx_kernel(const float* __restrict__ qx_b,
                                                 float* __restrict__ dst, int par) {
    extern __shared__ __align__(16) char smem[];
    const uint32_t sb = s2u(smem);
    const int tid = threadIdx.x;
    const int wid = tid >> 5;
    const int lane = tid & 31;
    const int warp_m = wid >> 2;
    const int warp_n = wid & 3;
    const int n0 = blockIdx.x * QROWS;

    const char* gA = (const char*)gAqx3[par];
    const char* gB = (const char*)(gBqx + (size_t)blockIdx.x * (QCH * 2 * QROWS * 64));

    float acc[4][6][4];
#pragma unroll
    for (int i = 0; i < 4; i++)
#pragma unroll
        for (int j = 0; j < 6; j++)
#pragma unroll
            for (int q = 0; q < 4; q++) acc[i][j][q] = 0.0f;

    const int a_row = lane & 15;
    const int a_coff = (lane >> 4) << 4;
    const int b_row = ((lane >> 4) << 3) | (lane & 7);
    const int b_coff = ((lane >> 3) & 1) << 4;

    load_stage_qx(sb, gA, gB, tid);
    load_stage_qx(sb + QSTG, gA + 32768, gB + 49152, tid);

    for (int c = 0; c < QCH; c++) {
        asm volatile("cp.async.wait_group 1;" ::: "memory");
        __syncthreads();

        const uint32_t As = sb + (c & 1) * QSTG;
        const uint32_t Bs = As + STAGE_A2;
#pragma unroll
        for (int ks = 0; ks < 4; ks++) {
            uint32_t ah[4][4], al[4][4];
#pragma unroll
            for (int mi = 0; mi < 4; mi++) {
                uint32_t ar = (uint32_t)(warp_m * 64 + mi * 16 + a_row);
                ldmatrix_x4(ah[mi], As + ar * PITCH + ks * 32 + a_coff);
                ldmatrix_x4(al[mi], As + (ar + 128) * PITCH + ks * 32 + a_coff);
            }
#pragma unroll
            for (int jp = 0; jp < 3; jp++) {
                uint32_t bh[4], bl[4];
                uint32_t br = (uint32_t)(warp_n * 48 + jp * 16 + b_row);
                ldmatrix_x4(bh, Bs + br * PITCH + ks * 32 + b_coff);
                ldmatrix_x4(bl, Bs + (br + 192) * PITCH + ks * 32 + b_coff);
#pragma unroll
                for (int mi = 0; mi < 4; mi++) {
                    mma16816(acc[mi][jp * 2 + 0], ah[mi], bh[0], bh[1]);
                    mma16816(acc[mi][jp * 2 + 1], ah[mi], bh[2], bh[3]);
                    mma16816(acc[mi][jp * 2 + 0], al[mi], bh[0], bh[1]);
                    mma16816(acc[mi][jp * 2 + 1], al[mi], bh[2], bh[3]);
                    mma16816(acc[mi][jp * 2 + 0], ah[mi], bl[0], bl[1]);
                    mma16816(acc[mi][jp * 2 + 1], ah[mi], bl[2], bl[3]);
                }
            }
        }
        __syncthreads();
        if (c + 2 < QCH)
            load_stage_qx(sb + (c & 1) * QSTG, gA + (size_t)(c + 2) * 32768,
                          gB + (size_t)(c + 2) * 49152, tid);
        else
            asm volatile("cp.async.commit_group;" ::: "memory");
    }

    const int g = lane >> 2, tq = lane & 3;
#pragma unroll
    for (int mi = 0; mi < 4; mi++) {
        int row = warp_m * 64 + mi * 16 + g;
#pragma unroll
        for (int nj = 0; nj < 6; nj++) {
            int col = n0 + warp_n * 48 + nj * 8 + 2 * tq;
            if (col >= Vv) continue;
            float b0 = qx_b[col], b1 = qx_b[col + 1];
            float2 v0 = make_float2(acc[mi][nj][0] + b0, acc[mi][nj][1] + b1);
            float2 v1 = make_float2(acc[mi][nj][2] + b0, acc[mi][nj][3] + b1);
            *(float2*)(dst + (size_t)row * Vv + col) = v0;
            *(float2*)(dst + (size_t)(row + 8) * Vv + col) = v1;
        }
    }
}

// In-place log_softmax over rows of length V
__global__ void softmax_kernel(float* __restrict__ base) {
    float* x = base + (size_t)blockIdx.x * Vv;
    __shared__ float sred[16];
    __shared__ float sval;
    const int tid = threadIdx.x;
    float m = -3.4e38f;
    for (int i = tid; i < Vv; i += 512) m = fmaxf(m, x[i]);
#pragma unroll
    for (int o = 16; o; o >>= 1) m = fmaxf(m, __shfl_xor_sync(0xffffffffu, m, o));
    if ((tid & 31) == 0) sred[tid >> 5] = m;
    __syncthreads();
    if (tid < 32) {
        float v = (tid < 16) ? sred[tid] : -3.4e38f;
#pragma unroll
        for (int o = 8; o; o >>= 1) v = fmaxf(v, __shfl_xor_sync(0xffffffffu, v, o));
        if (tid == 0) sval = v;
    }
    __syncthreads();
    m = sval;
    float s = 0.0f;
    for (int i = tid; i < Vv; i += 512) s += expf(x[i] - m);
#pragma unroll
    for (int o = 16; o; o >>= 1) s += __shfl_xor_sync(0xffffffffu, s, o);
    __syncthreads();
    if ((tid & 31) == 0) sred[tid >> 5] = s;
    __syncthreads();
    if (tid < 32) {
        float v = (tid < 16) ? sred[tid] : 0.0f;
#pragma unroll
        for (int o = 8; o; o >>= 1) v += __shfl_xor_sync(0xffffffffu, v, o);
        if (tid == 0) sval = m + logf(v);
    }
    __syncthreads();
    float lz = sval;
    for (int i = tid; i < Vv; i += 512) x[i] -= lz;
}

extern "C" void kernel_launch(void* const* d_in, const int* in_sizes, int n_in,
                              void* d_out, int out_size) {
    const float* features = (const float*)d_in[0];
    const int* captions = (const int*)d_in[1];
    const float* noise   = (const float*)d_in[3];
    const float* embed_W = (const float*)d_in[4];
    const float* W_ih    = (const float*)d_in[5];
    const float* W_hh    = (const float*)d_in[6];
    const float* b_ih    = (const float*)d_in[7];
    const float* b_hh    = (const float*)d_in[8];
    const float* qz_W    = (const float*)d_in[9];
    const float* qz_b    = (const float*)d_in[10];
    const float* prior_W = (const float*)d_in[11];
    const float* prior_b = (const float*)d_in[12];
    const float* qx_W    = (const float*)d_in[13];
    const float* qx_b    = (const float*)d_in[14];
    float* out = (float*)d_out;

    static cudaStream_t s1 = nullptr, s2 = nullptr;
    static cudaEvent_t evZ = nullptr, evQ[3] = {nullptr, nullptr, nullptr};
    static cudaEvent_t evJ1 = nullptr, evJ2 = nullptr;
    if (s1 == nullptr) {
        cudaStreamCreateWithFlags(&s1, cudaStreamNonBlocking);
        cudaStreamCreateWithFlags(&s2, cudaStreamNonBlocking);
        cudaEventCreateWithFlags(&evZ, cudaEventDisableTiming);
        for (int i = 0; i < 3; i++) cudaEventCreateWithFlags(&evQ[i], cudaEventDisableTiming);
        cudaEventCreateWithFlags(&evJ1, cudaEventDisableTiming);
        cudaEventCreateWithFlags(&evJ2, cudaEventDisableTiming);
    }

    cudaFuncSetAttribute(pqz_kernel, cudaFuncAttributeMaxDynamicSharedMemorySize, SM128);
    cudaFuncSetAttribute(gatesepi_kernel, cudaFuncAttributeMaxDynamicSharedMemorySize, SM128);
    cudaFuncSetAttribute(qx_kernel, cudaFuncAttributeMaxDynamicSharedMemorySize, SMQX);

    // one-time prep
    prep_misc_kernel<<<(PREP_MISC_TOT + 255) / 256, 256>>>(b_ih, b_hh, qz_b, prior_b,
                                                           embed_W, captions);
    prep_wg_kernel<<<(2048 * 320 + 255) / 256, 256>>>(W_ih, W_hh);
    prep_wpq_kernel<<<(1024 * 256 + 255) / 256, 256>>>(qz_W, prior_W);
    prep_wqx_kernel<<<(16128 * 192 + 255) / 256, 256>>>(qx_W);

    // initial LSTM step: features through the gates tc path (z,h image sections are zero)
    build_feat_kernel<<<32, 512>>>(features);
    gatesepi_kernel<<<48, 256, SM128>>>(0);

    for (int t = 0; t < Tt; t++) {
        pqz_kernel<<<48, 256, SM128>>>(noise, out, t);
        cudaEventRecord(evZ, 0);
        cudaStreamWaitEvent(s1, evZ, 0);
        float* qx_dst = out + OFF_QX + (size_t)t * Bb * Vv;
        qx_kernel<<<NT_QX, 256, SMQX, s1>>>(qx_b, qx_dst, t % 3);
        cudaEventRecord(evQ[t % 3], s1);
        cudaStreamWaitEvent(s2, evQ[t % 3], 0);
        softmax_kernel<<<128, 512, 0, s2>>>(qx_dst);
        // gatesepi(t+1) writes qx A-buffer (t+1)%3, last read by qx(t-2)
        if (t >= 2) cudaStreamWaitEvent(0, evQ[(t + 1) % 3], 0);
        gatesepi_kernel<<<48, 256, SM128>>>(t + 1);
    }

    cudaEventRecord(evJ1, s1);
    cudaStreamWaitEvent(0, evJ1, 0);
    cudaEventRecord(evJ2, s2);
    cudaStreamWaitEvent(0, evJ2, 0);
}